// round 5
// baseline (speedup 1.0000x reference)
#include <cuda_runtime.h>
#include <math.h>

// ---------------------------------------------------------------------------
// MetaQDA via conditioned Woodbury / matrix-determinant-lemma restructuring.
//   S_c = L L^T + V_c^T V_c,   V_c = [x_i - xbar (32 rows); sqrt(kappa*N/kN)(xbar - m)]
//   S^{-1} = L^{-T}(I - T^T M^{-1} T)L^{-1},  T = V L^{-T} (33 x D),  M = I + T T^T (SPD)
//   logdet S = 2 sum log|L_ii| + logdet M
// GEMM core: 128x128x8 double-buffered, packed fma.rn.f32x2 (FFMA2), with
// triangular k-range skipping for all products involving L^{-1}.
// ---------------------------------------------------------------------------

#define Dd   1024
#define Cc   32
#define SHOTSn 32
#define NSUP 1024
#define Qq   1024
#define KW   34     // rows of T-hat per class: 32 centered + scaled-diff + mu(aux)
#define KV   33     // rows entering the Woodbury capacitance M
#define NU   (Cc * KW)   // 1088

// ------------------------- scratch (device globals) -------------------------
__device__ float g_L[Dd * Dd];
__device__ float g_Linv[Dd * Dd];
__device__ float g_Tmp[512 * 512];
__device__ float g_W[NU * Dd];
__device__ float g_T[NU * Dd];
__device__ float g_G[Qq * Dd];
__device__ float g_U[Qq * NU];          // [q][c*KW + k]
__device__ float g_TtT[Cc * KW * KW];
__device__ float g_Kinv[Cc * KW * KW];  // packed KV x KV per class
__device__ float g_b[Cc * KW];
__device__ float g_mu[Cc * Dd];
__device__ float g_xbar[Cc * Dd];
__device__ float g_Gn2[Qq];
__device__ float g_qn2[Qq];
__device__ float g_mun2[Cc];
__device__ float g_qm[Qq * Cc];
__device__ int   g_sample_of[Cc * SHOTSn];

struct Cls {
    float Nj, kN, common_, scale;
    float bias, coefD, inv_common, invscale_half, hh;
};
__device__ Cls   g_cls[Cc];
__device__ float g_kappa_;
__device__ float g_sumlogL;

// ------------------------------ f32x2 FMA ------------------------------------
__device__ __forceinline__ unsigned long long ffma2(unsigned long long a,
                                                    unsigned long long b,
                                                    unsigned long long c) {
    unsigned long long d;
    asm("fma.rn.f32x2 %0, %1, %2, %3;" : "=l"(d) : "l"(a), "l"(b), "l"(c));
    return d;
}

// ------------------------------- setup --------------------------------------
__global__ void setup_kernel(const int* __restrict__ labels,
                             const float* __restrict__ kappa_p,
                             const float* __restrict__ nu_p,
                             const float* __restrict__ triu_diag) {
    __shared__ int   sl[NSUP];
    __shared__ float red[32];
    int t = threadIdx.x;  // 1024 threads
    sl[t] = labels[t];
    g_sample_of[t] = 0;
    __syncthreads();

    int l = sl[t];
    int cnt = 0;
    for (int j = 0; j < t; j++) cnt += (sl[j] == l);
    if (l >= 0 && l < Cc && cnt < SHOTSn) g_sample_of[l * SHOTSn + cnt] = t;

    float v = logf(fabsf(triu_diag[t]));
    for (int o = 16; o > 0; o >>= 1) v += __shfl_down_sync(0xffffffffu, v, o);
    if ((t & 31) == 0) red[t >> 5] = v;
    __syncthreads();
    if (t < 32) {
        float s = red[t];
        for (int o = 16; o > 0; o >>= 1) s += __shfl_down_sync(0xffffffffu, s, o);
        if (t == 0) g_sumlogL = s;
    }

    if (t < Cc) {
        int nj = 0;
        for (int j = 0; j < NSUP; j++) nj += (sl[j] == t);
        float kappa_ = fabsf(*kappa_p) + 1e-6f;
        float nu_    = fmaxf(*nu_p, (float)(Dd - 1) + 1e-6f);
        float Njf = (float)nj;
        float kN = kappa_ + Njf;
        float common_ = nu_ + Njf + 1.0f - (float)Dd;
        float scale = (kN + 1.0f) / (common_ * kN);
        Cls c;
        c.Nj = Njf; c.kN = kN; c.common_ = common_; c.scale = scale;
        c.bias = 0.f;
        c.coefD = 0.5f * (common_ + (float)Dd);
        c.inv_common = 1.0f / common_;
        c.invscale_half = 0.5f / scale;
        c.hh = 0.f;
        g_cls[t] = c;
        if (t == 0) g_kappa_ = kappa_;
    }
}

// --------------------------- build L (and zero Linv) -------------------------
__global__ void build_L_kernel(const float* __restrict__ tdiag,
                               const float* __restrict__ tlower) {
    int idx = blockIdx.x * blockDim.x + threadIdx.x;
    if (idx >= Dd * Dd) return;
    int i = idx / Dd, j = idx % Dd;
    float v = (i == j) ? fabsf(tdiag[i]) : (i > j ? tlower[idx] : 0.0f);
    g_L[idx] = v;
    g_Linv[idx] = 0.0f;
}

// ------------------ invert 32x32 lower-triangular diagonal blocks ------------
__global__ void inv_diag_kernel() {
    __shared__ float Ls[32][33];
    __shared__ float Xs[32][33];
    int b = blockIdx.x, t = threadIdx.x;  // 32 threads
    int off = b * 32;
    for (int i = 0; i < 32; i++) Ls[i][t] = g_L[(off + i) * Dd + off + t];
    __syncthreads();
    for (int i = 0; i < 32; i++) {
        float s = (i == t) ? 1.0f : 0.0f;
        for (int k = t; k < i; k++) s -= Ls[i][k] * Xs[k][t];
        Xs[i][t] = (i >= t) ? s / Ls[i][i] : 0.0f;
    }
    __syncthreads();
    for (int i = 0; i < 32; i++) g_Linv[(off + i) * Dd + off + t] = Xs[i][t];
}

// --------------------- small generic SGEMM (64x64x16, 4x4) -------------------
template <bool TRANSB>
__global__ void sgemm_kernel(const float* __restrict__ A, long long sA, int lda,
                             const float* __restrict__ B, long long sB, int ldb,
                             float* __restrict__ Cp, long long sC, int ldc,
                             int M, int N, int K, float alpha) {
    __shared__ float As[16][65];
    __shared__ float Bs[16][65];
    A  += blockIdx.z * sA;
    B  += blockIdx.z * sB;
    Cp += blockIdx.z * sC;
    int m0 = blockIdx.y * 64, n0 = blockIdx.x * 64;
    int tid = threadIdx.x;  // 256
    int tm = (tid / 16) * 4;
    int tn = (tid % 16) * 4;
    float acc[4][4] = {};
    for (int k0 = 0; k0 < K; k0 += 16) {
#pragma unroll
        for (int i = 0; i < 4; i++) {
            int idx = tid + i * 256;
            int am = idx / 16, ak = idx % 16;
            float v = 0.f;
            if (m0 + am < M && k0 + ak < K) v = A[(long long)(m0 + am) * lda + k0 + ak];
            As[ak][am] = v;
        }
#pragma unroll
        for (int i = 0; i < 4; i++) {
            int idx = tid + i * 256;
            if (!TRANSB) {
                int bk = idx / 64, bn = idx % 64;
                float v = 0.f;
                if (k0 + bk < K && n0 + bn < N) v = B[(long long)(k0 + bk) * ldb + n0 + bn];
                Bs[bk][bn] = v;
            } else {
                int bn = idx / 16, bk = idx % 16;
                float v = 0.f;
                if (k0 + bk < K && n0 + bn < N) v = B[(long long)(n0 + bn) * ldb + k0 + bk];
                Bs[bk][bn] = v;
            }
        }
        __syncthreads();
#pragma unroll
        for (int k = 0; k < 16; k++) {
            float a[4], b[4];
#pragma unroll
            for (int i = 0; i < 4; i++) a[i] = As[k][tm + i];
#pragma unroll
            for (int j = 0; j < 4; j++) b[j] = Bs[k][tn + j];
#pragma unroll
            for (int i = 0; i < 4; i++)
#pragma unroll
                for (int j = 0; j < 4; j++) acc[i][j] += a[i] * b[j];
        }
        __syncthreads();
    }
#pragma unroll
    for (int i = 0; i < 4; i++) {
        int m = m0 + tm + i;
        if (m >= M) continue;
#pragma unroll
        for (int j = 0; j < 4; j++) {
            int n = n0 + tn + j;
            if (n >= N) continue;
            Cp[(long long)m * ldc + n] = alpha * acc[i][j];
        }
    }
}

// ----------- fast SGEMM core (128x128x8, 8x8 via f32x2, dbuf) ----------------
// Requires kbeg/kend multiples of 8 (here multiples of 128). Row-major.
// A is stored duplicated in smem so {a,a} pairs load as one 8-byte LDS.
template <bool TRANSB>
__device__ __forceinline__ void sgemm128_core(
    const float* __restrict__ A, int lda,
    const float* __restrict__ B, int ldb,
    float* __restrict__ Cp, int ldc,
    int M, int N, int K, float alpha, int m0, int n0, int kbeg, int kend) {
    __shared__ __align__(16) float Asd[2][8][264];  // [k][2*m] duplicated
    __shared__ __align__(16) float Bs[2][8][132];   // [k][n]
    const int tid = threadIdx.x;              // 256
    const int tx = tid & 15, ty = tid >> 4;
    const int arow = tid >> 1, ak4 = (tid & 1) * 4;   // A (and B if TRANSB) loads
    const int bk = tid >> 5, bn4 = (tid & 31) * 4;    // B loads if !TRANSB
    const int t0 = kbeg >> 3, t1 = kend >> 3;

    float4 ar, br;
    const float4 fz = make_float4(0.f, 0.f, 0.f, 0.f);

    // ---- prefetch tile t0 ----
    ar = (m0 + arow < M) ? *(const float4*)(A + (long long)(m0 + arow) * lda + kbeg + ak4) : fz;
    if (TRANSB) {
        br = (n0 + arow < N) ? *(const float4*)(B + (long long)(n0 + arow) * ldb + kbeg + ak4) : fz;
    } else {
        if (n0 + bn4 + 3 < N) {
            br = *(const float4*)(B + (long long)(kbeg + bk) * ldb + n0 + bn4);
        } else {
            const float* Bp = B + (long long)(kbeg + bk) * ldb;
            br.x = (n0 + bn4 + 0 < N) ? Bp[n0 + bn4 + 0] : 0.f;
            br.y = (n0 + bn4 + 1 < N) ? Bp[n0 + bn4 + 1] : 0.f;
            br.z = (n0 + bn4 + 2 < N) ? Bp[n0 + bn4 + 2] : 0.f;
            br.w = (n0 + bn4 + 3 < N) ? Bp[n0 + bn4 + 3] : 0.f;
        }
    }
    {
        *(float2*)&Asd[0][ak4 + 0][2 * arow] = make_float2(ar.x, ar.x);
        *(float2*)&Asd[0][ak4 + 1][2 * arow] = make_float2(ar.y, ar.y);
        *(float2*)&Asd[0][ak4 + 2][2 * arow] = make_float2(ar.z, ar.z);
        *(float2*)&Asd[0][ak4 + 3][2 * arow] = make_float2(ar.w, ar.w);
        if (TRANSB) {
            Bs[0][ak4 + 0][arow] = br.x; Bs[0][ak4 + 1][arow] = br.y;
            Bs[0][ak4 + 2][arow] = br.z; Bs[0][ak4 + 3][arow] = br.w;
        } else {
            *(float4*)&Bs[0][bk][bn4] = br;
        }
    }
    __syncthreads();

    unsigned long long acc2[8][4] = {};  // 8 m-rows x 4 packed n-pairs
    for (int t = t0; t < t1; t++) {
        const int buf = (t - t0) & 1;
        const int kn = (t + 1) << 3;
        if (t + 1 < t1) {
            ar = (m0 + arow < M) ? *(const float4*)(A + (long long)(m0 + arow) * lda + kn + ak4) : fz;
            if (TRANSB) {
                br = (n0 + arow < N) ? *(const float4*)(B + (long long)(n0 + arow) * ldb + kn + ak4) : fz;
            } else {
                if (n0 + bn4 + 3 < N) {
                    br = *(const float4*)(B + (long long)(kn + bk) * ldb + n0 + bn4);
                } else {
                    const float* Bp = B + (long long)(kn + bk) * ldb;
                    br.x = (n0 + bn4 + 0 < N) ? Bp[n0 + bn4 + 0] : 0.f;
                    br.y = (n0 + bn4 + 1 < N) ? Bp[n0 + bn4 + 1] : 0.f;
                    br.z = (n0 + bn4 + 2 < N) ? Bp[n0 + bn4 + 2] : 0.f;
                    br.w = (n0 + bn4 + 3 < N) ? Bp[n0 + bn4 + 3] : 0.f;
                }
            }
        }
#pragma unroll
        for (int k = 0; k < 8; k++) {
            unsigned long long a2[8], b2[4];
#pragma unroll
            for (int i = 0; i < 8; i++)
                a2[i] = *(const unsigned long long*)&Asd[buf][k][(ty * 8 + i) * 2];
#pragma unroll
            for (int j = 0; j < 4; j++)
                b2[j] = *(const unsigned long long*)&Bs[buf][k][tx * 8 + j * 2];
#pragma unroll
            for (int i = 0; i < 8; i++)
#pragma unroll
                for (int j = 0; j < 4; j++) acc2[i][j] = ffma2(a2[i], b2[j], acc2[i][j]);
        }
        if (t + 1 < t1) {
            const int b2i = (t + 1 - t0) & 1;
            *(float2*)&Asd[b2i][ak4 + 0][2 * arow] = make_float2(ar.x, ar.x);
            *(float2*)&Asd[b2i][ak4 + 1][2 * arow] = make_float2(ar.y, ar.y);
            *(float2*)&Asd[b2i][ak4 + 2][2 * arow] = make_float2(ar.z, ar.z);
            *(float2*)&Asd[b2i][ak4 + 3][2 * arow] = make_float2(ar.w, ar.w);
            if (TRANSB) {
                Bs[b2i][ak4 + 0][arow] = br.x; Bs[b2i][ak4 + 1][arow] = br.y;
                Bs[b2i][ak4 + 2][arow] = br.z; Bs[b2i][ak4 + 3][arow] = br.w;
            } else {
                *(float4*)&Bs[b2i][bk][bn4] = br;
            }
        }
        __syncthreads();
    }

#pragma unroll
    for (int i = 0; i < 8; i++) {
        int m = m0 + ty * 8 + i;
        if (m >= M) continue;
        float* Cr = Cp + (long long)m * ldc;
#pragma unroll
        for (int j = 0; j < 4; j++) {
            int n = n0 + tx * 8 + 2 * j;
            float lo = __uint_as_float((unsigned int)acc2[i][j]);
            float hi = __uint_as_float((unsigned int)(acc2[i][j] >> 32));
            if (n < N)     Cr[n]     = alpha * lo;
            if (n + 1 < N) Cr[n + 1] = alpha * hi;
        }
    }
}

// kbmode: 0 -> kbeg=0, 1 -> kbeg=n0 (B lower-triangular, !TRANSB)
// kemode: 0 -> kend=K, 1 -> kend=m0+128 (A lower-tri), 2 -> kend=n0+128 (B^T of lower-tri)
template <bool TRANSB>
__global__ __launch_bounds__(256, 2)
void sgemm128_kernel(const float* __restrict__ A, long long sA, int lda,
                     const float* __restrict__ B, long long sB, int ldb,
                     float* __restrict__ Cp, long long sC, int ldc,
                     int M, int N, int K, float alpha, int kbmode, int kemode) {
    int m0 = blockIdx.y * 128, n0 = blockIdx.x * 128;
    int kb = (kbmode == 1) ? n0 : 0;
    int ke = (kemode == 1) ? min(K, m0 + 128) : ((kemode == 2) ? min(K, n0 + 128) : K);
    sgemm128_core<TRANSB>(A + blockIdx.z * sA, lda, B + blockIdx.z * sB, ldb,
                          Cp + blockIdx.z * sC, ldc, M, N, K, alpha, m0, n0, kb, ke);
}

// Fused T = W @ Linv^T and G = query @ Linv^T (shared B = Linv, lower-tri skip).
__global__ __launch_bounds__(256, 2)
void sgemm128_dual_kernel(const float* __restrict__ A1, int M1, int nby1,
                          const float* __restrict__ A2, int M2,
                          const float* __restrict__ B,
                          float* __restrict__ C1, float* __restrict__ C2) {
    const float* A;
    float* Cp;
    int M, m0;
    if ((int)blockIdx.y < nby1) {
        A = A1; Cp = C1; M = M1; m0 = blockIdx.y * 128;
    } else {
        A = A2; Cp = C2; M = M2; m0 = (blockIdx.y - nby1) * 128;
    }
    int n0 = blockIdx.x * 128;
    sgemm128_core<true>(A, Dd, B, Dd, Cp, Dd, M, Dd, Dd, 1.0f,
                        m0, n0, 0, min(Dd, n0 + 128));
}

// ------------------------- per-class means (xbar, mu) ------------------------
__global__ void build_mu_kernel(const float* __restrict__ support,
                                const float* __restrict__ m) {
    int idx = blockIdx.x * blockDim.x + threadIdx.x;  // over C * D
    if (idx >= Cc * Dd) return;
    int c = idx / Dd, d = idx % Dd;
    float s = 0.f;
    for (int j = 0; j < SHOTSn; j++)
        s += support[(long long)g_sample_of[c * SHOTSn + j] * Dd + d];
    float xbar = s / g_cls[c].Nj;
    float mu = (g_kappa_ * m[d] + s) / g_cls[c].kN;
    g_xbar[idx] = xbar;
    g_mu[idx] = mu;
}

// ------------------------------- build W -------------------------------------
__global__ void build_W_kernel(const float* __restrict__ support,
                               const float* __restrict__ m) {
    int idx = blockIdx.x * blockDim.x + threadIdx.x;
    if (idx >= Cc * KW * Dd) return;
    int d = idx % Dd;
    int row = idx / Dd;
    int c = row / KW;
    int k = row % KW;
    float v;
    if (k < SHOTSn) {
        v = support[(long long)g_sample_of[c * SHOTSn + k] * Dd + d] - g_xbar[c * Dd + d];
    } else if (k == SHOTSn) {
        Cls cl = g_cls[c];
        float c2 = sqrtf(g_kappa_ * cl.Nj / cl.kN);
        v = c2 * (g_xbar[c * Dd + d] - m[d]);
    } else {
        v = g_mu[c * Dd + d];
    }
    g_W[idx] = v;
}

// ------------------------------- row norms -----------------------------------
__global__ void rownorm_kernel(const float* __restrict__ X, int ld, float* __restrict__ out) {
    int r = blockIdx.x, t = threadIdx.x;  // 256 threads
    const float* row = X + (long long)r * ld;
    float s = 0.f;
    for (int j = t; j < ld; j += blockDim.x) { float v = row[j]; s += v * v; }
    __shared__ float red[8];
    for (int o = 16; o > 0; o >>= 1) s += __shfl_down_sync(0xffffffffu, s, o);
    if ((t & 31) == 0) red[t >> 5] = s;
    __syncthreads();
    if (t < 32) {
        float v = (t < 8) ? red[t] : 0.f;
        for (int o = 4; o > 0; o >>= 1) v += __shfl_down_sync(0xffffffffu, v, o);
        if (t == 0) out[r] = v;
    }
}

// -------- per-class SPD 33x33 inverse (fp64 Gauss-Jordan) + logdet/bias ------
__global__ void small_inv_kernel() {
    int c = blockIdx.x, t = threadIdx.x;  // 64 threads
    __shared__ double Ms[KV][KV + 1];
    __shared__ double Iv[KV][KV + 1];
    __shared__ double s_logdet;
    __shared__ int    s_piv;
    const float* TtT = g_TtT + c * KW * KW;
    for (int i = t; i < KV * KV; i += blockDim.x) {
        int r = i / KV, cc = i % KV;
        Ms[r][cc] = (double)TtT[r * KW + cc] + (r == cc ? 1.0 : 0.0);  // M = I + T T^T
        Iv[r][cc] = (r == cc) ? 1.0 : 0.0;
    }
    if (t < KV) g_b[c * KW + t] = TtT[t * KW + (KW - 1)];  // t_a . t_mu
    if (t == 0) s_logdet = 0.0;
    __syncthreads();
    for (int k = 0; k < KV; k++) {
        if (t == 0) {
            int p = k; double best = fabs(Ms[k][k]);
            for (int r = k + 1; r < KV; r++) {
                double a = fabs(Ms[r][k]);
                if (a > best) { best = a; p = r; }
            }
            s_piv = p;
        }
        __syncthreads();
        int p = s_piv;
        if (p != k && t < KV) {
            double tmp = Ms[k][t]; Ms[k][t] = Ms[p][t]; Ms[p][t] = tmp;
            tmp = Iv[k][t]; Iv[k][t] = Iv[p][t]; Iv[p][t] = tmp;
        }
        __syncthreads();
        double piv = Ms[k][k];
        if (t == 0) s_logdet += log(fabs(piv));
        double pivinv = 1.0 / piv;
        if (t < KV) { Ms[k][t] *= pivinv; Iv[k][t] *= pivinv; }
        __syncthreads();
        if (t < KV && t != k) {
            double f = Ms[t][k];
            for (int j = 0; j < KV; j++) {
                Ms[t][j] -= f * Ms[k][j];
                Iv[t][j] -= f * Iv[k][j];
            }
        }
        __syncthreads();
    }
    for (int i = t; i < KV * KV; i += blockDim.x)
        g_Kinv[c * KW * KW + i] = (float)Iv[i / KV][i % KV];
    if (t == 0) {
        Cls cl = g_cls[c];
        double logdetS = 2.0 * (double)g_sumlogL + s_logdet;
        double logdet_sigma = (double)Dd * log((double)cl.scale) + logdetS;
        double common_ = (double)cl.common_;
        double bias = lgamma(0.5 * (common_ + (double)Dd)) - lgamma(0.5 * common_)
                    - 0.5 * (double)Dd * log(common_) - 0.5 * logdet_sigma;
        g_cls[c].bias = (float)bias;
        g_cls[c].hh = TtT[(KW - 1) * KW + (KW - 1)];  // ||t_mu||^2
    }
}

// --------------------------------- finalize ----------------------------------
__global__ void finalize_kernel(float* __restrict__ out) {
    int c = blockIdx.y;
    int q = blockIdx.x * blockDim.x + threadIdx.x;
    __shared__ float Ks[KV * KV];
    __shared__ float bs[KV];
    __shared__ Cls cl;
    for (int i = threadIdx.x; i < KV * KV; i += blockDim.x) Ks[i] = g_Kinv[c * KW * KW + i];
    if (threadIdx.x < KV) bs[threadIdx.x] = g_b[c * KW + threadIdx.x];
    if (threadIdx.x == 0) cl = g_cls[c];
    __syncthreads();
    if (q >= Qq) return;
    const float* Ur = g_U + (long long)q * NU + c * KW;
    float v[KV];
    float u33 = Ur[KW - 1];  // g . t_mu
#pragma unroll
    for (int i = 0; i < KV; i++) v[i] = Ur[i] - bs[i];  // u_a = t_a.(g - t_mu)
    float s = 0.f;
#pragma unroll 4
    for (int i = 0; i < KV; i++) {
        float acc = 0.f;
#pragma unroll
        for (int j = 0; j < KV; j++) acc += Ks[i * KV + j] * v[j];
        s += v[i] * acc;
    }
    float distA = g_Gn2[q] - 2.0f * u33 + cl.hh - s;
    float dist  = cl.invscale_half * distA
                + 0.5f * (g_qn2[q] - 2.0f * g_qm[q * Cc + c] + g_mun2[c]);
    out[(long long)q * Cc + c] = cl.bias - cl.coefD * log1pf(dist * cl.inv_common);
}

// ------------------------------ host launchers -------------------------------
static void sgemm_small(const float* A, long long sA, int lda,
                        const float* B, long long sB, int ldb,
                        float* Cmat, long long sC, int ldc,
                        int M, int N, int K, float alpha, bool transB, int batch) {
    dim3 grid((N + 63) / 64, (M + 63) / 64, batch);
    if (transB)
        sgemm_kernel<true><<<grid, 256>>>(A, sA, lda, B, sB, ldb, Cmat, sC, ldc, M, N, K, alpha);
    else
        sgemm_kernel<false><<<grid, 256>>>(A, sA, lda, B, sB, ldb, Cmat, sC, ldc, M, N, K, alpha);
}

static void sgemm_big(const float* A, long long sA, int lda,
                      const float* B, long long sB, int ldb,
                      float* Cmat, long long sC, int ldc,
                      int M, int N, int K, float alpha, bool transB, int batch,
                      int kbmode, int kemode) {
    dim3 grid((N + 127) / 128, (M + 127) / 128, batch);
    if (transB)
        sgemm128_kernel<true><<<grid, 256>>>(A, sA, lda, B, sB, ldb, Cmat, sC, ldc,
                                             M, N, K, alpha, kbmode, kemode);
    else
        sgemm128_kernel<false><<<grid, 256>>>(A, sA, lda, B, sB, ldb, Cmat, sC, ldc,
                                              M, N, K, alpha, kbmode, kemode);
}

extern "C" void kernel_launch(void* const* d_in, const int* in_sizes, int n_in,
                              void* d_out, int out_size) {
    const float* support = (const float*)d_in[0];
    const float* query   = (const float*)d_in[1];
    const int*   labels  = (const int*)d_in[2];
    const float* m       = (const float*)d_in[3];
    const float* kappa   = (const float*)d_in[4];
    const float* nu      = (const float*)d_in[5];
    const float* tdiag   = (const float*)d_in[6];
    const float* tlower  = (const float*)d_in[7];
    float* out = (float*)d_out;

    float *pL, *pLinv, *pTmp, *pW, *pT, *pG, *pU, *pTtT, *pMu, *pGn2, *pqn2, *pmun2, *pQm;
    cudaGetSymbolAddress((void**)&pL, g_L);
    cudaGetSymbolAddress((void**)&pLinv, g_Linv);
    cudaGetSymbolAddress((void**)&pTmp, g_Tmp);
    cudaGetSymbolAddress((void**)&pW, g_W);
    cudaGetSymbolAddress((void**)&pT, g_T);
    cudaGetSymbolAddress((void**)&pG, g_G);
    cudaGetSymbolAddress((void**)&pU, g_U);
    cudaGetSymbolAddress((void**)&pTtT, g_TtT);
    cudaGetSymbolAddress((void**)&pMu, g_mu);
    cudaGetSymbolAddress((void**)&pGn2, g_Gn2);
    cudaGetSymbolAddress((void**)&pqn2, g_qn2);
    cudaGetSymbolAddress((void**)&pmun2, g_mun2);
    cudaGetSymbolAddress((void**)&pQm, g_qm);

    // 1) scalars, per-class params, stable sample gather, sum log|diag L|
    setup_kernel<<<1, NSUP>>>(labels, kappa, nu, tdiag);

    // 2) per-class xbar / mu, then W = [X_c - xbar | sqrt(.)*(xbar-m) | mu_c]
    build_mu_kernel<<<(Cc * Dd + 255) / 256, 256>>>(support, m);
    build_W_kernel<<<(Cc * KW * Dd + 255) / 256, 256>>>(support, m);

    // 3) L and L^{-1} (recursive-doubling blocked triangular inverse)
    build_L_kernel<<<(Dd * Dd + 255) / 256, 256>>>(tdiag, tlower);
    inv_diag_kernel<<<32, 32>>>();
    for (int lev = 1; lev <= 5; lev++) {
        int s = 32 << (lev - 1);
        int pairs = 32 >> lev;
        long long stride = 2LL * s * (Dd + 1);
        if (s < 128) {
            sgemm_small(pL + (long long)s * Dd, stride, Dd,
                        pLinv, stride, Dd,
                        pTmp, (long long)s * s, s,
                        s, s, s, 1.0f, false, pairs);
            sgemm_small(pLinv + (long long)s * Dd + s, stride, Dd,
                        pTmp, (long long)s * s, s,
                        pLinv + (long long)s * Dd, stride, Dd,
                        s, s, s, -1.0f, false, pairs);
        } else {
            // Tmp = B_blk (dense) @ Ainv (lower-tri): k runs [n0, s)
            sgemm_big(pL + (long long)s * Dd, stride, Dd,
                      pLinv, stride, Dd,
                      pTmp, (long long)s * s, s,
                      s, s, s, 1.0f, false, pairs, /*kb*/1, /*ke*/0);
            // block = -Cinv (lower-tri) @ Tmp: k runs [0, m0+128)
            sgemm_big(pLinv + (long long)s * Dd + s, stride, Dd,
                      pTmp, (long long)s * s, s,
                      pLinv + (long long)s * Dd, stride, Dd,
                      s, s, s, -1.0f, false, pairs, /*kb*/0, /*ke*/1);
        }
    }

    // 4+5) fused: T = W @ Linv^T [1088x1024] and G = query @ Linv^T [1024x1024]
    {
        int nby1 = (NU + 127) / 128;       // 9
        int nby2 = (Qq + 127) / 128;       // 8
        dim3 grid(Dd / 128, nby1 + nby2);  // (8, 17)
        sgemm128_dual_kernel<<<grid, 256>>>(pW, NU, nby1, query, Qq, pLinv, pT, pG);
    }

    // 6) row norms: ||L^{-1}q||^2, ||q||^2, ||mu||^2
    rownorm_kernel<<<Qq, 256>>>(pG, Dd, pGn2);
    rownorm_kernel<<<Qq, 256>>>(query, Dd, pqn2);
    rownorm_kernel<<<Cc, 256>>>(pMu, Dd, pmun2);

    // 7) T^T T per class [34x34]; M = I + [0:33,0:33] inverted in fp64 + logdet/bias
    sgemm_small(pT, (long long)KW * Dd, Dd, pT, (long long)KW * Dd, Dd,
                pTtT, (long long)KW * KW, KW, KW, KW, Dd, 1.0f, true, Cc);
    small_inv_kernel<<<Cc, 64>>>();

    // 8) U = G @ T^T  [1024 x 1088]  (dense)
    sgemm_big(pG, 0, Dd, pT, 0, Dd, pU, 0, NU, Qq, NU, Dd, 1.0f, true, 1, 0, 0);

    // 9) qm = query @ mu^T  [Q x C]
    sgemm_small(query, 0, Dd, pMu, 0, Dd, pQm, 0, Cc, Qq, Cc, Dd, 1.0f, true, 1);

    // 10) fuse quadratic forms + bias + log1p
    finalize_kernel<<<dim3((Qq + 127) / 128, Cc), 128>>>(out);
}

// round 6
// speedup vs baseline: 1.3224x; 1.3224x over previous
#include <cuda_runtime.h>
#include <math.h>

// ---------------------------------------------------------------------------
// MetaQDA via conditioned Woodbury / matrix-determinant-lemma restructuring.
//   S_c = L L^T + V_c^T V_c,   V_c = [x_i - xbar (32 rows); sqrt(kappa*N/kN)(xbar - m)]
//   S^{-1} = L^{-T}(I - T^T M^{-1} T)L^{-1},  T = V L^{-T} (33 x D),  M = I + T T^T (SPD)
//   logdet S = 2 sum log|L_ii| + logdet M
// GEMM core: 128x128x8 double-buffered, packed fma.rn.f32x2, conflict-free
// smem (duplicated-A broadcast loads, float4 B loads + register pair packing).
// All large GEMMs are K-split across extra blocks (partial buffers + reduce)
// to fill the chip; the trtri chain levels run 16-64 blocks each instead of
// 4-16.
// ---------------------------------------------------------------------------

#define Dd   1024
#define Cc   32
#define SHOTSn 32
#define NSUP 1024
#define Qq   1024
#define KW   34     // rows of T-hat per class: 32 centered + scaled-diff + mu(aux)
#define KV   33     // rows entering the Woodbury capacitance M
#define NU   (Cc * KW)   // 1088
#define NUQ  (NU + Qq)   // 2112

// ------------------------- scratch (device globals) -------------------------
__device__ float g_L[Dd * Dd];
__device__ float g_Linv[Dd * Dd];
__device__ float g_Tmp[512 * 512];
__device__ float g_W[NU * Dd];
__device__ float g_TG[NUQ * Dd];        // T (first NU rows) then G (Qq rows)
__device__ float g_U[Qq * NU];          // [q][c*KW + k]
__device__ float g_Part[2 * NUQ * Dd];  // K-split partial buffer (max user: dual)
__device__ float g_TtT[Cc * KW * KW];
__device__ float g_Kinv[Cc * KW * KW];  // packed KV x KV per class
__device__ float g_b[Cc * KW];
__device__ float g_mu[Cc * Dd];
__device__ float g_xbar[Cc * Dd];
__device__ float g_Gn2[Qq];
__device__ float g_qn2[Qq];
__device__ float g_mun2[Cc];
__device__ float g_qm[Qq * Cc];
__device__ int   g_sample_of[Cc * SHOTSn];

struct Cls {
    float Nj, kN, common_, scale;
    float bias, coefD, inv_common, invscale_half, hh;
};
__device__ Cls   g_cls[Cc];
__device__ float g_kappa_;
__device__ float g_sumlogL;

// ------------------------------ f32x2 helpers --------------------------------
__device__ __forceinline__ unsigned long long ffma2(unsigned long long a,
                                                    unsigned long long b,
                                                    unsigned long long c) {
    unsigned long long d;
    asm("fma.rn.f32x2 %0, %1, %2, %3;" : "=l"(d) : "l"(a), "l"(b), "l"(c));
    return d;
}
__device__ __forceinline__ unsigned long long pack2(float lo, float hi) {
    unsigned long long r;
    asm("mov.b64 %0, {%1, %2};" : "=l"(r) : "f"(lo), "f"(hi));
    return r;
}

// ------------------------------- setup --------------------------------------
__global__ void setup_kernel(const int* __restrict__ labels,
                             const float* __restrict__ kappa_p,
                             const float* __restrict__ nu_p,
                             const float* __restrict__ triu_diag) {
    __shared__ int   sl[NSUP];
    __shared__ float red[32];
    int t = threadIdx.x;  // 1024 threads
    sl[t] = labels[t];
    g_sample_of[t] = 0;
    __syncthreads();

    int l = sl[t];
    int cnt = 0;
    for (int j = 0; j < t; j++) cnt += (sl[j] == l);
    if (l >= 0 && l < Cc && cnt < SHOTSn) g_sample_of[l * SHOTSn + cnt] = t;

    float v = logf(fabsf(triu_diag[t]));
    for (int o = 16; o > 0; o >>= 1) v += __shfl_down_sync(0xffffffffu, v, o);
    if ((t & 31) == 0) red[t >> 5] = v;
    __syncthreads();
    if (t < 32) {
        float s = red[t];
        for (int o = 16; o > 0; o >>= 1) s += __shfl_down_sync(0xffffffffu, s, o);
        if (t == 0) g_sumlogL = s;
    }

    if (t < Cc) {
        int nj = 0;
        for (int j = 0; j < NSUP; j++) nj += (sl[j] == t);
        float kappa_ = fabsf(*kappa_p) + 1e-6f;
        float nu_    = fmaxf(*nu_p, (float)(Dd - 1) + 1e-6f);
        float Njf = (float)nj;
        float kN = kappa_ + Njf;
        float common_ = nu_ + Njf + 1.0f - (float)Dd;
        float scale = (kN + 1.0f) / (common_ * kN);
        Cls c;
        c.Nj = Njf; c.kN = kN; c.common_ = common_; c.scale = scale;
        c.bias = 0.f;
        c.coefD = 0.5f * (common_ + (float)Dd);
        c.inv_common = 1.0f / common_;
        c.invscale_half = 0.5f / scale;
        c.hh = 0.f;
        g_cls[t] = c;
        if (t == 0) g_kappa_ = kappa_;
    }
}

// --------------------------- build L (and zero Linv) -------------------------
__global__ void build_L_kernel(const float* __restrict__ tdiag,
                               const float* __restrict__ tlower) {
    int idx = blockIdx.x * blockDim.x + threadIdx.x;
    if (idx >= Dd * Dd) return;
    int i = idx / Dd, j = idx % Dd;
    float v = (i == j) ? fabsf(tdiag[i]) : (i > j ? tlower[idx] : 0.0f);
    g_L[idx] = v;
    g_Linv[idx] = 0.0f;
}

// ------------------ invert 32x32 lower-triangular diagonal blocks ------------
__global__ void inv_diag_kernel() {
    __shared__ float Ls[32][33];
    __shared__ float Xs[32][33];
    int b = blockIdx.x, t = threadIdx.x;  // 32 threads
    int off = b * 32;
    for (int i = 0; i < 32; i++) Ls[i][t] = g_L[(off + i) * Dd + off + t];
    __syncthreads();
    for (int i = 0; i < 32; i++) {
        float s = (i == t) ? 1.0f : 0.0f;
        for (int k = t; k < i; k++) s -= Ls[i][k] * Xs[k][t];
        Xs[i][t] = (i >= t) ? s / Ls[i][i] : 0.0f;
    }
    __syncthreads();
    for (int i = 0; i < 32; i++) g_Linv[(off + i) * Dd + off + t] = Xs[i][t];
}

// --------------------- small generic SGEMM (64x64x16, 4x4) -------------------
template <bool TRANSB>
__global__ void sgemm_kernel(const float* __restrict__ A, long long sA, int lda,
                             const float* __restrict__ B, long long sB, int ldb,
                             float* __restrict__ Cp, long long sC, int ldc,
                             int M, int N, int K, float alpha) {
    __shared__ float As[16][65];
    __shared__ float Bs[16][65];
    A  += blockIdx.z * sA;
    B  += blockIdx.z * sB;
    Cp += blockIdx.z * sC;
    int m0 = blockIdx.y * 64, n0 = blockIdx.x * 64;
    int tid = threadIdx.x;  // 256
    int tm = (tid / 16) * 4;
    int tn = (tid % 16) * 4;
    float acc[4][4] = {};
    for (int k0 = 0; k0 < K; k0 += 16) {
#pragma unroll
        for (int i = 0; i < 4; i++) {
            int idx = tid + i * 256;
            int am = idx / 16, ak = idx % 16;
            float v = 0.f;
            if (m0 + am < M && k0 + ak < K) v = A[(long long)(m0 + am) * lda + k0 + ak];
            As[ak][am] = v;
        }
#pragma unroll
        for (int i = 0; i < 4; i++) {
            int idx = tid + i * 256;
            if (!TRANSB) {
                int bk = idx / 64, bn = idx % 64;
                float v = 0.f;
                if (k0 + bk < K && n0 + bn < N) v = B[(long long)(k0 + bk) * ldb + n0 + bn];
                Bs[bk][bn] = v;
            } else {
                int bn = idx / 16, bk = idx % 16;
                float v = 0.f;
                if (k0 + bk < K && n0 + bn < N) v = B[(long long)(n0 + bn) * ldb + k0 + bk];
                Bs[bk][bn] = v;
            }
        }
        __syncthreads();
#pragma unroll
        for (int k = 0; k < 16; k++) {
            float a[4], b[4];
#pragma unroll
            for (int i = 0; i < 4; i++) a[i] = As[k][tm + i];
#pragma unroll
            for (int j = 0; j < 4; j++) b[j] = Bs[k][tn + j];
#pragma unroll
            for (int i = 0; i < 4; i++)
#pragma unroll
                for (int j = 0; j < 4; j++) acc[i][j] += a[i] * b[j];
        }
        __syncthreads();
    }
#pragma unroll
    for (int i = 0; i < 4; i++) {
        int m = m0 + tm + i;
        if (m >= M) continue;
#pragma unroll
        for (int j = 0; j < 4; j++) {
            int n = n0 + tn + j;
            if (n >= N) continue;
            Cp[(long long)m * ldc + n] = alpha * acc[i][j];
        }
    }
}

// -------- fast SGEMM core (128x128x8, 8x8 via f32x2, dbuf, conflict-free) ----
// A duplicated in smem ({a,a} broadcast LDS.64); B float4 LDS.128 + reg pack.
template <bool TRANSB>
__device__ __forceinline__ void sgemm128_core(
    const float* __restrict__ A, int lda,
    const float* __restrict__ B, int ldb,
    float* __restrict__ Cp, int ldc,
    int M, int N, float alpha, int m0, int n0, int kbeg, int kend) {
    __shared__ __align__(16) float Asd[2][8][264];  // [k][2*m] duplicated
    __shared__ __align__(16) float Bs[2][8][132];   // [k][n]
    const int tid = threadIdx.x;              // 256
    const int tx = tid & 15, ty = tid >> 4;
    const int arow = tid >> 1, ak4 = (tid & 1) * 4;   // A (and B if TRANSB) loads
    const int bk = tid >> 5, bn4 = (tid & 31) * 4;    // B loads if !TRANSB

    unsigned long long acc2[8][4] = {};  // 8 m-rows x 4 packed n-pairs

    if (kend > kbeg) {
        const int t0 = kbeg >> 3, t1 = kend >> 3;
        float4 ar, br;
        const float4 fz = make_float4(0.f, 0.f, 0.f, 0.f);

        ar = (m0 + arow < M) ? *(const float4*)(A + (long long)(m0 + arow) * lda + kbeg + ak4) : fz;
        if (TRANSB) {
            br = (n0 + arow < N) ? *(const float4*)(B + (long long)(n0 + arow) * ldb + kbeg + ak4) : fz;
        } else {
            if (n0 + bn4 + 3 < N) {
                br = *(const float4*)(B + (long long)(kbeg + bk) * ldb + n0 + bn4);
            } else {
                const float* Bp = B + (long long)(kbeg + bk) * ldb;
                br.x = (n0 + bn4 + 0 < N) ? Bp[n0 + bn4 + 0] : 0.f;
                br.y = (n0 + bn4 + 1 < N) ? Bp[n0 + bn4 + 1] : 0.f;
                br.z = (n0 + bn4 + 2 < N) ? Bp[n0 + bn4 + 2] : 0.f;
                br.w = (n0 + bn4 + 3 < N) ? Bp[n0 + bn4 + 3] : 0.f;
            }
        }
        *(float2*)&Asd[0][ak4 + 0][2 * arow] = make_float2(ar.x, ar.x);
        *(float2*)&Asd[0][ak4 + 1][2 * arow] = make_float2(ar.y, ar.y);
        *(float2*)&Asd[0][ak4 + 2][2 * arow] = make_float2(ar.z, ar.z);
        *(float2*)&Asd[0][ak4 + 3][2 * arow] = make_float2(ar.w, ar.w);
        if (TRANSB) {
            Bs[0][ak4 + 0][arow] = br.x; Bs[0][ak4 + 1][arow] = br.y;
            Bs[0][ak4 + 2][arow] = br.z; Bs[0][ak4 + 3][arow] = br.w;
        } else {
            *(float4*)&Bs[0][bk][bn4] = br;
        }
        __syncthreads();

        for (int t = t0; t < t1; t++) {
            const int buf = (t - t0) & 1;
            const int kn = (t + 1) << 3;
            if (t + 1 < t1) {
                ar = (m0 + arow < M) ? *(const float4*)(A + (long long)(m0 + arow) * lda + kn + ak4) : fz;
                if (TRANSB) {
                    br = (n0 + arow < N) ? *(const float4*)(B + (long long)(n0 + arow) * ldb + kn + ak4) : fz;
                } else {
                    if (n0 + bn4 + 3 < N) {
                        br = *(const float4*)(B + (long long)(kn + bk) * ldb + n0 + bn4);
                    } else {
                        const float* Bp = B + (long long)(kn + bk) * ldb;
                        br.x = (n0 + bn4 + 0 < N) ? Bp[n0 + bn4 + 0] : 0.f;
                        br.y = (n0 + bn4 + 1 < N) ? Bp[n0 + bn4 + 1] : 0.f;
                        br.z = (n0 + bn4 + 2 < N) ? Bp[n0 + bn4 + 2] : 0.f;
                        br.w = (n0 + bn4 + 3 < N) ? Bp[n0 + bn4 + 3] : 0.f;
                    }
                }
            }
#pragma unroll
            for (int k = 0; k < 8; k++) {
                unsigned long long a2[8], b2[4];
#pragma unroll
                for (int i = 0; i < 8; i++)
                    a2[i] = *(const unsigned long long*)&Asd[buf][k][(ty * 8 + i) * 2];
                float4 bf0 = *(const float4*)&Bs[buf][k][tx * 8];
                float4 bf1 = *(const float4*)&Bs[buf][k][tx * 8 + 4];
                b2[0] = pack2(bf0.x, bf0.y);
                b2[1] = pack2(bf0.z, bf0.w);
                b2[2] = pack2(bf1.x, bf1.y);
                b2[3] = pack2(bf1.z, bf1.w);
#pragma unroll
                for (int i = 0; i < 8; i++)
#pragma unroll
                    for (int j = 0; j < 4; j++) acc2[i][j] = ffma2(a2[i], b2[j], acc2[i][j]);
            }
            if (t + 1 < t1) {
                const int b2i = (t + 1 - t0) & 1;
                *(float2*)&Asd[b2i][ak4 + 0][2 * arow] = make_float2(ar.x, ar.x);
                *(float2*)&Asd[b2i][ak4 + 1][2 * arow] = make_float2(ar.y, ar.y);
                *(float2*)&Asd[b2i][ak4 + 2][2 * arow] = make_float2(ar.z, ar.z);
                *(float2*)&Asd[b2i][ak4 + 3][2 * arow] = make_float2(ar.w, ar.w);
                if (TRANSB) {
                    Bs[b2i][ak4 + 0][arow] = br.x; Bs[b2i][ak4 + 1][arow] = br.y;
                    Bs[b2i][ak4 + 2][arow] = br.z; Bs[b2i][ak4 + 3][arow] = br.w;
                } else {
                    *(float4*)&Bs[b2i][bk][bn4] = br;
                }
            }
            __syncthreads();
        }
    }

#pragma unroll
    for (int i = 0; i < 8; i++) {
        int m = m0 + ty * 8 + i;
        if (m >= M) continue;
        float* Cr = Cp + (long long)m * ldc;
#pragma unroll
        for (int j = 0; j < 4; j++) {
            int n = n0 + tx * 8 + 2 * j;
            float lo = __uint_as_float((unsigned int)acc2[i][j]);
            float hi = __uint_as_float((unsigned int)(acc2[i][j] >> 32));
            if (n < N)     Cr[n]     = alpha * lo;
            if (n + 1 < N) Cr[n + 1] = alpha * hi;
        }
    }
}

// -------------------- K-split wrapper: writes partial chunks -----------------
// blockIdx.z = pair * nsplit + chunk. Partial layout: [(pair*nsplit+chunk)][M*N].
// kbmode: 1 -> kbeg >= n0 (B lower-tri, !TRANSB). kemode: 1 -> kend <= m0+128
// (A lower-tri); 2 -> kend <= n0+128 (B^T with B lower-tri, TRANSB).
template <bool TRANSB>
__global__ __launch_bounds__(256, 2)
void sgemm128_split_kernel(const float* __restrict__ A, long long sA, int lda,
                           const float* __restrict__ B, long long sB, int ldb,
                           float* __restrict__ part,
                           int M, int N, int K, int nsplit, int kchunk,
                           int kbmode, int kemode) {
    int pair = blockIdx.z / nsplit;
    int chunk = blockIdx.z % nsplit;
    int m0 = blockIdx.y * 128, n0 = blockIdx.x * 128;
    int kb = chunk * kchunk;
    int ke = min(kb + kchunk, K);
    if (kbmode == 1) kb = max(kb, n0);
    if (kemode == 1) ke = min(ke, m0 + 128);
    if (kemode == 2) ke = min(ke, n0 + 128);
    float* Cp = part + (long long)blockIdx.z * M * N;
    sgemm128_core<TRANSB>(A + pair * sA, lda, B + pair * sB, ldb,
                          Cp, N, M, N, 1.0f, m0, n0, kb, ke);
}

// Fused T|G (stacked) = [W; query] @ Linv^T with K-split + lower-tri clipping.
__global__ __launch_bounds__(256, 2)
void sgemm128_dual_split_kernel(const float* __restrict__ A1, int nby1,
                                const float* __restrict__ A2,
                                const float* __restrict__ B,
                                float* __restrict__ part, int kchunk) {
    int chunk = blockIdx.z;
    const float* A;
    int M, m0, rowoff;
    if ((int)blockIdx.y < nby1) {
        A = A1; M = NU; m0 = blockIdx.y * 128; rowoff = 0;
    } else {
        A = A2; M = Qq; m0 = (blockIdx.y - nby1) * 128; rowoff = NU;
    }
    int n0 = blockIdx.x * 128;
    int kb = chunk * kchunk;
    int ke = min(min(kb + kchunk, Dd), n0 + 128);   // Linv lower-tri
    float* Cp = part + (long long)chunk * NUQ * Dd + (long long)rowoff * Dd;
    sgemm128_core<true>(A, Dd, B, Dd, Cp, Dd, M, Dd, 1.0f, m0, n0, kb, ke);
}

// -------------------- reduce partial chunks into output ----------------------
__global__ void reduce_kernel(const float* __restrict__ part, float* __restrict__ out,
                              int nsplit, int M, int N, int ldc, long long sOut,
                              float alpha, int pairs) {
    long long idx = (long long)blockIdx.x * blockDim.x + threadIdx.x;
    long long total = (long long)pairs * M * N;
    if (idx >= total) return;
    int pair = (int)(idx / ((long long)M * N));
    long long rem = idx - (long long)pair * M * N;
    int mm = (int)(rem / N);
    int nn = (int)(rem - (long long)mm * N);
    const float* p = part + (long long)pair * nsplit * M * N + rem;
    float s = 0.f;
    for (int c = 0; c < nsplit; c++) s += p[(long long)c * M * N];
    out[pair * sOut + (long long)mm * ldc + nn] = alpha * s;
}

// ------------------------- per-class means (xbar, mu) ------------------------
__global__ void build_mu_kernel(const float* __restrict__ support,
                                const float* __restrict__ m) {
    int idx = blockIdx.x * blockDim.x + threadIdx.x;  // over C * D
    if (idx >= Cc * Dd) return;
    int c = idx / Dd, d = idx % Dd;
    float s = 0.f;
    for (int j = 0; j < SHOTSn; j++)
        s += support[(long long)g_sample_of[c * SHOTSn + j] * Dd + d];
    float xbar = s / g_cls[c].Nj;
    float mu = (g_kappa_ * m[d] + s) / g_cls[c].kN;
    g_xbar[idx] = xbar;
    g_mu[idx] = mu;
}

// ------------------------------- build W -------------------------------------
__global__ void build_W_kernel(const float* __restrict__ support,
                               const float* __restrict__ m) {
    int idx = blockIdx.x * blockDim.x + threadIdx.x;
    if (idx >= Cc * KW * Dd) return;
    int d = idx % Dd;
    int row = idx / Dd;
    int c = row / KW;
    int k = row % KW;
    float v;
    if (k < SHOTSn) {
        v = support[(long long)g_sample_of[c * SHOTSn + k] * Dd + d] - g_xbar[c * Dd + d];
    } else if (k == SHOTSn) {
        Cls cl = g_cls[c];
        float c2 = sqrtf(g_kappa_ * cl.Nj / cl.kN);
        v = c2 * (g_xbar[c * Dd + d] - m[d]);
    } else {
        v = g_mu[c * Dd + d];
    }
    g_W[idx] = v;
}

// ------------------------------- row norms -----------------------------------
__global__ void rownorm_kernel(const float* __restrict__ X, int ld, float* __restrict__ out) {
    int r = blockIdx.x, t = threadIdx.x;  // 256 threads
    const float* row = X + (long long)r * ld;
    float s = 0.f;
    for (int j = t; j < ld; j += blockDim.x) { float v = row[j]; s += v * v; }
    __shared__ float red[8];
    for (int o = 16; o > 0; o >>= 1) s += __shfl_down_sync(0xffffffffu, s, o);
    if ((t & 31) == 0) red[t >> 5] = s;
    __syncthreads();
    if (t < 32) {
        float v = (t < 8) ? red[t] : 0.f;
        for (int o = 4; o > 0; o >>= 1) v += __shfl_down_sync(0xffffffffu, v, o);
        if (t == 0) out[r] = v;
    }
}

// -------- per-class SPD 33x33 inverse (fp64 Gauss-Jordan) + logdet/bias ------
__global__ void small_inv_kernel() {
    int c = blockIdx.x, t = threadIdx.x;  // 64 threads
    __shared__ double Ms[KV][KV + 1];
    __shared__ double Iv[KV][KV + 1];
    __shared__ double s_logdet;
    __shared__ int    s_piv;
    const float* TtT = g_TtT + c * KW * KW;
    for (int i = t; i < KV * KV; i += blockDim.x) {
        int r = i / KV, cc = i % KV;
        Ms[r][cc] = (double)TtT[r * KW + cc] + (r == cc ? 1.0 : 0.0);  // M = I + T T^T
        Iv[r][cc] = (r == cc) ? 1.0 : 0.0;
    }
    if (t < KV) g_b[c * KW + t] = TtT[t * KW + (KW - 1)];  // t_a . t_mu
    if (t == 0) s_logdet = 0.0;
    __syncthreads();
    for (int k = 0; k < KV; k++) {
        if (t == 0) {
            int p = k; double best = fabs(Ms[k][k]);
            for (int r = k + 1; r < KV; r++) {
                double a = fabs(Ms[r][k]);
                if (a > best) { best = a; p = r; }
            }
            s_piv = p;
        }
        __syncthreads();
        int p = s_piv;
        if (p != k && t < KV) {
            double tmp = Ms[k][t]; Ms[k][t] = Ms[p][t]; Ms[p][t] = tmp;
            tmp = Iv[k][t]; Iv[k][t] = Iv[p][t]; Iv[p][t] = tmp;
        }
        __syncthreads();
        double piv = Ms[k][k];
        if (t == 0) s_logdet += log(fabs(piv));
        double pivinv = 1.0 / piv;
        if (t < KV) { Ms[k][t] *= pivinv; Iv[k][t] *= pivinv; }
        __syncthreads();
        if (t < KV && t != k) {
            double f = Ms[t][k];
            for (int j = 0; j < KV; j++) {
                Ms[t][j] -= f * Ms[k][j];
                Iv[t][j] -= f * Iv[k][j];
            }
        }
        __syncthreads();
    }
    for (int i = t; i < KV * KV; i += blockDim.x)
        g_Kinv[c * KW * KW + i] = (float)Iv[i / KV][i % KV];
    if (t == 0) {
        Cls cl = g_cls[c];
        double logdetS = 2.0 * (double)g_sumlogL + s_logdet;
        double logdet_sigma = (double)Dd * log((double)cl.scale) + logdetS;
        double common_ = (double)cl.common_;
        double bias = lgamma(0.5 * (common_ + (double)Dd)) - lgamma(0.5 * common_)
                    - 0.5 * (double)Dd * log(common_) - 0.5 * logdet_sigma;
        g_cls[c].bias = (float)bias;
        g_cls[c].hh = TtT[(KW - 1) * KW + (KW - 1)];  // ||t_mu||^2
    }
}

// --------------------------------- finalize ----------------------------------
__global__ void finalize_kernel(float* __restrict__ out) {
    int c = blockIdx.y;
    int q = blockIdx.x * blockDim.x + threadIdx.x;
    __shared__ float Ks[KV * KV];
    __shared__ float bs[KV];
    __shared__ Cls cl;
    for (int i = threadIdx.x; i < KV * KV; i += blockDim.x) Ks[i] = g_Kinv[c * KW * KW + i];
    if (threadIdx.x < KV) bs[threadIdx.x] = g_b[c * KW + threadIdx.x];
    if (threadIdx.x == 0) cl = g_cls[c];
    __syncthreads();
    if (q >= Qq) return;
    const float* Ur = g_U + (long long)q * NU + c * KW;
    float v[KV];
    float u33 = Ur[KW - 1];  // g . t_mu
#pragma unroll
    for (int i = 0; i < KV; i++) v[i] = Ur[i] - bs[i];  // u_a = t_a.(g - t_mu)
    float s = 0.f;
#pragma unroll 4
    for (int i = 0; i < KV; i++) {
        float acc = 0.f;
#pragma unroll
        for (int j = 0; j < KV; j++) acc += Ks[i * KV + j] * v[j];
        s += v[i] * acc;
    }
    float distA = g_Gn2[q] - 2.0f * u33 + cl.hh - s;
    float dist  = cl.invscale_half * distA
                + 0.5f * (g_qn2[q] - 2.0f * g_qm[q * Cc + c] + g_mun2[c]);
    out[(long long)q * Cc + c] = cl.bias - cl.coefD * log1pf(dist * cl.inv_common);
}

// ------------------------------ host launchers -------------------------------
static void sgemm_small(const float* A, long long sA, int lda,
                        const float* B, long long sB, int ldb,
                        float* Cmat, long long sC, int ldc,
                        int M, int N, int K, float alpha, bool transB, int batch) {
    dim3 grid((N + 63) / 64, (M + 63) / 64, batch);
    if (transB)
        sgemm_kernel<true><<<grid, 256>>>(A, sA, lda, B, sB, ldb, Cmat, sC, ldc, M, N, K, alpha);
    else
        sgemm_kernel<false><<<grid, 256>>>(A, sA, lda, B, sB, ldb, Cmat, sC, ldc, M, N, K, alpha);
}

static void sgemm_big_split(const float* A, long long sA, int lda,
                            const float* B, long long sB, int ldb,
                            float* part, float* out, long long sOut, int ldc,
                            int M, int N, int K, float alpha, bool transB, int pairs,
                            int nsplit, int kchunk, int kbmode, int kemode) {
    dim3 grid((N + 127) / 128, (M + 127) / 128, pairs * nsplit);
    if (transB)
        sgemm128_split_kernel<true><<<grid, 256>>>(A, sA, lda, B, sB, ldb, part,
                                                   M, N, K, nsplit, kchunk, kbmode, kemode);
    else
        sgemm128_split_kernel<false><<<grid, 256>>>(A, sA, lda, B, sB, ldb, part,
                                                    M, N, K, nsplit, kchunk, kbmode, kemode);
    long long total = (long long)pairs * M * N;
    reduce_kernel<<<(unsigned)((total + 255) / 256), 256>>>(part, out, nsplit, M, N, ldc,
                                                            sOut, alpha, pairs);
}

extern "C" void kernel_launch(void* const* d_in, const int* in_sizes, int n_in,
                              void* d_out, int out_size) {
    const float* support = (const float*)d_in[0];
    const float* query   = (const float*)d_in[1];
    const int*   labels  = (const int*)d_in[2];
    const float* m       = (const float*)d_in[3];
    const float* kappa   = (const float*)d_in[4];
    const float* nu      = (const float*)d_in[5];
    const float* tdiag   = (const float*)d_in[6];
    const float* tlower  = (const float*)d_in[7];
    float* out = (float*)d_out;

    float *pL, *pLinv, *pTmp, *pW, *pTG, *pU, *pPart, *pTtT, *pMu, *pGn2, *pqn2, *pmun2, *pQm;
    cudaGetSymbolAddress((void**)&pL, g_L);
    cudaGetSymbolAddress((void**)&pLinv, g_Linv);
    cudaGetSymbolAddress((void**)&pTmp, g_Tmp);
    cudaGetSymbolAddress((void**)&pW, g_W);
    cudaGetSymbolAddress((void**)&pTG, g_TG);
    cudaGetSymbolAddress((void**)&pU, g_U);
    cudaGetSymbolAddress((void**)&pPart, g_Part);
    cudaGetSymbolAddress((void**)&pTtT, g_TtT);
    cudaGetSymbolAddress((void**)&pMu, g_mu);
    cudaGetSymbolAddress((void**)&pGn2, g_Gn2);
    cudaGetSymbolAddress((void**)&pqn2, g_qn2);
    cudaGetSymbolAddress((void**)&pmun2, g_mun2);
    cudaGetSymbolAddress((void**)&pQm, g_qm);
    float* pT = pTG;                 // T: rows 0..NU-1
    float* pG = pTG + (long long)NU * Dd;  // G: rows NU..NU+Qq-1

    // 1) scalars, per-class params, stable sample gather, sum log|diag L|
    setup_kernel<<<1, NSUP>>>(labels, kappa, nu, tdiag);

    // 2) per-class xbar / mu, then W = [X_c - xbar | sqrt(.)*(xbar-m) | mu_c]
    build_mu_kernel<<<(Cc * Dd + 255) / 256, 256>>>(support, m);
    build_W_kernel<<<(Cc * KW * Dd + 255) / 256, 256>>>(support, m);

    // 3) L and L^{-1} (recursive-doubling blocked triangular inverse)
    build_L_kernel<<<(Dd * Dd + 255) / 256, 256>>>(tdiag, tlower);
    inv_diag_kernel<<<32, 32>>>();
    // small levels (s = 32, 64): batched 64-tile SGEMM
    for (int lev = 1; lev <= 2; lev++) {
        int s = 32 << (lev - 1);
        int pairs = 32 >> lev;
        long long stride = 2LL * s * (Dd + 1);
        sgemm_small(pL + (long long)s * Dd, stride, Dd,
                    pLinv, stride, Dd,
                    pTmp, (long long)s * s, s,
                    s, s, s, 1.0f, false, pairs);
        sgemm_small(pLinv + (long long)s * Dd + s, stride, Dd,
                    pTmp, (long long)s * s, s,
                    pLinv + (long long)s * Dd, stride, Dd,
                    s, s, s, -1.0f, false, pairs);
    }
    // big levels (s = 128, 256, 512): K-split fast SGEMM
    for (int lev = 3; lev <= 5; lev++) {
        int s = 32 << (lev - 1);
        int pairs = 32 >> lev;
        long long stride = 2LL * s * (Dd + 1);
        int nsplit = (s == 128) ? 4 : ((s == 256) ? 4 : 4);
        int kchunk = s / nsplit;  // 32 / 64 / 128 (multiples of 8)
        // Tmp = B_blk (dense) @ Ainv (lower-tri):  kbeg >= n0
        sgemm_big_split(pL + (long long)s * Dd, stride, Dd,
                        pLinv, stride, Dd,
                        pPart, pTmp, (long long)s * s, s,
                        s, s, s, 1.0f, false, pairs, nsplit, kchunk, 1, 0);
        // block = -Cinv (lower-tri) @ Tmp:  kend <= m0+128
        sgemm_big_split(pLinv + (long long)s * Dd + s, stride, Dd,
                        pTmp, (long long)s * s, s,
                        pPart, pLinv + (long long)s * Dd, stride, Dd,
                        s, s, s, -1.0f, false, pairs, nsplit, kchunk, 0, 1);
    }

    // 4+5) fused K-split: [T; G] = [W; query] @ Linv^T  (stacked 2112 x 1024)
    {
        int nby1 = (NU + 127) / 128;       // 9
        int nby2 = (Qq + 127) / 128;       // 8
        dim3 grid(Dd / 128, nby1 + nby2, 2);  // (8, 17, 2)
        sgemm128_dual_split_kernel<<<grid, 256>>>(pW, nby1, query, pLinv, pPart, Dd / 2);
        long long total = (long long)NUQ * Dd;
        reduce_kernel<<<(unsigned)((total + 255) / 256), 256>>>(pPart, pTG, 2, NUQ, Dd, Dd,
                                                                0, 1.0f, 1);
    }

    // 6) row norms: ||L^{-1}q||^2, ||q||^2, ||mu||^2
    rownorm_kernel<<<Qq, 256>>>(pG, Dd, pGn2);
    rownorm_kernel<<<Qq, 256>>>(query, Dd, pqn2);
    rownorm_kernel<<<Cc, 256>>>(pMu, Dd, pmun2);

    // 7) T^T T per class [34x34]; M = I + [0:33,0:33] inverted in fp64 + logdet/bias
    sgemm_small(pT, (long long)KW * Dd, Dd, pT, (long long)KW * Dd, Dd,
                pTtT, (long long)KW * KW, KW, KW, KW, Dd, 1.0f, true, Cc);
    small_inv_kernel<<<Cc, 64>>>();

    // 8) U = G @ T^T  [1024 x 1088]  K-split x2
    sgemm_big_split(pG, 0, Dd, pT, 0, Dd,
                    pPart, pU, 0, NU,
                    Qq, NU, Dd, 1.0f, true, 1, 2, Dd / 2, 0, 0);

    // 9) qm = query @ mu^T  [Q x C]
    sgemm_small(query, 0, Dd, pMu, 0, Dd, pQm, 0, Cc, Qq, Cc, Dd, 1.0f, true, 1);

    // 10) fuse quadratic forms + bias + log1p
    finalize_kernel<<<dim3((Qq + 127) / 128, Cc), 128>>>(out);
}

// round 8
// speedup vs baseline: 1.4803x; 1.1194x over previous
#include <cuda_runtime.h>
#include <math.h>

// ---------------------------------------------------------------------------
// MetaQDA via conditioned Woodbury / matrix-determinant-lemma restructuring.
//   S_c = L L^T + V_c^T V_c,   V_c = [x_i - xbar (32 rows); sqrt(kappa*N/kN)(xbar - m)]
//   S^{-1} = L^{-T}(I - T^T M^{-1} T)L^{-1},  T = V L^{-T} (33 x D),  M = I + T T^T (SPD)
//   logdet S = 2 sum log|L_ii| + logdet M
// GEMM core: 128x128x8 double-buffered, packed fma.rn.f32x2, conflict-free
// smem; NO occupancy cap (register spills kill the mainloop otherwise).
// All large GEMMs are K-split across blocks (partial buffers + reduce).
// ---------------------------------------------------------------------------

#define Dd   1024
#define Cc   32
#define SHOTSn 32
#define NSUP 1024
#define Qq   1024
#define KW   34     // rows of T-hat per class: 32 centered + scaled-diff + mu(aux)
#define KV   33     // rows entering the Woodbury capacitance M
#define NU   (Cc * KW)   // 1088
#define NUQ  (NU + Qq)   // 2112

// ------------------------- scratch (device globals) -------------------------
__device__ float g_L[Dd * Dd];
__device__ float g_Linv[Dd * Dd];
__device__ float g_Tmp[512 * 512];
__device__ float g_W[NU * Dd];
__device__ float g_TG[NUQ * Dd];        // T (first NU rows) then G (Qq rows)
__device__ float g_U[Qq * NU];          // [q][c*KW + k]
__device__ float g_Part[4 * NUQ * Dd];  // K-split partial buffer
__device__ float g_TtT[Cc * KW * KW];
__device__ float g_Kinv[Cc * KW * KW];  // packed KV x KV per class
__device__ float g_b[Cc * KW];
__device__ float g_mu[Cc * Dd];
__device__ float g_xbar[Cc * Dd];
__device__ float g_Gn2[Qq];
__device__ float g_qn2[Qq];
__device__ float g_mun2[Cc];
__device__ float g_qm[Qq * Cc];
__device__ int   g_sample_of[Cc * SHOTSn];

struct Cls {
    float Nj, kN, common_, scale;
    float bias, coefD, inv_common, invscale_half, hh;
};
__device__ Cls   g_cls[Cc];
__device__ float g_kappa_;
__device__ float g_sumlogL;

// ------------------------------ f32x2 helpers --------------------------------
__device__ __forceinline__ unsigned long long ffma2(unsigned long long a,
                                                    unsigned long long b,
                                                    unsigned long long c) {
    unsigned long long d;
    asm("fma.rn.f32x2 %0, %1, %2, %3;" : "=l"(d) : "l"(a), "l"(b), "l"(c));
    return d;
}
__device__ __forceinline__ unsigned long long pack2(float lo, float hi) {
    unsigned long long r;
    asm("mov.b64 %0, {%1, %2};" : "=l"(r) : "f"(lo), "f"(hi));
    return r;
}

// ------------------------------- setup --------------------------------------
__global__ void setup_kernel(const int* __restrict__ labels,
                             const float* __restrict__ kappa_p,
                             const float* __restrict__ nu_p,
                             const float* __restrict__ triu_diag) {
    __shared__ int   sl[NSUP];
    __shared__ float red[32];
    int t = threadIdx.x;  // 1024 threads
    sl[t] = labels[t];
    g_sample_of[t] = 0;
    __syncthreads();

    int l = sl[t];
    int cnt = 0;
    for (int j = 0; j < t; j++) cnt += (sl[j] == l);
    if (l >= 0 && l < Cc && cnt < SHOTSn) g_sample_of[l * SHOTSn + cnt] = t;

    float v = logf(fabsf(triu_diag[t]));
    for (int o = 16; o > 0; o >>= 1) v += __shfl_down_sync(0xffffffffu, v, o);
    if ((t & 31) == 0) red[t >> 5] = v;
    __syncthreads();
    if (t < 32) {
        float s = red[t];
        for (int o = 16; o > 0; o >>= 1) s += __shfl_down_sync(0xffffffffu, s, o);
        if (t == 0) g_sumlogL = s;
    }

    if (t < Cc) {
        int nj = 0;
        for (int j = 0; j < NSUP; j++) nj += (sl[j] == t);
        float kappa_ = fabsf(*kappa_p) + 1e-6f;
        float nu_    = fmaxf(*nu_p, (float)(Dd - 1) + 1e-6f);
        float Njf = (float)nj;
        float kN = kappa_ + Njf;
        float common_ = nu_ + Njf + 1.0f - (float)Dd;
        float scale = (kN + 1.0f) / (common_ * kN);
        Cls c;
        c.Nj = Njf; c.kN = kN; c.common_ = common_; c.scale = scale;
        c.bias = 0.f;
        c.coefD = 0.5f * (common_ + (float)Dd);
        c.inv_common = 1.0f / common_;
        c.invscale_half = 0.5f / scale;
        c.hh = 0.f;
        g_cls[t] = c;
        if (t == 0) g_kappa_ = kappa_;
    }
}

// --------------------------- build L (and zero Linv) -------------------------
__global__ void build_L_kernel(const float* __restrict__ tdiag,
                               const float* __restrict__ tlower) {
    int idx = blockIdx.x * blockDim.x + threadIdx.x;
    if (idx >= Dd * Dd) return;
    int i = idx / Dd, j = idx % Dd;
    float v = (i == j) ? fabsf(tdiag[i]) : (i > j ? tlower[idx] : 0.0f);
    g_L[idx] = v;
    g_Linv[idx] = 0.0f;
}

// ------------------ invert 32x32 lower-triangular diagonal blocks ------------
__global__ void inv_diag_kernel() {
    __shared__ float Ls[32][33];
    __shared__ float Xs[32][33];
    int b = blockIdx.x, t = threadIdx.x;  // 32 threads
    int off = b * 32;
    for (int i = 0; i < 32; i++) Ls[i][t] = g_L[(off + i) * Dd + off + t];
    __syncthreads();
    for (int i = 0; i < 32; i++) {
        float s = (i == t) ? 1.0f : 0.0f;
        for (int k = t; k < i; k++) s -= Ls[i][k] * Xs[k][t];
        Xs[i][t] = (i >= t) ? s / Ls[i][i] : 0.0f;
    }
    __syncthreads();
    for (int i = 0; i < 32; i++) g_Linv[(off + i) * Dd + off + t] = Xs[i][t];
}

// --------------------- small generic SGEMM (64x64x16, 4x4) -------------------
template <bool TRANSB>
__global__ void sgemm_kernel(const float* __restrict__ A, long long sA, int lda,
                             const float* __restrict__ B, long long sB, int ldb,
                             float* __restrict__ Cp, long long sC, int ldc,
                             int M, int N, int K, float alpha) {
    __shared__ float As[16][65];
    __shared__ float Bs[16][65];
    A  += blockIdx.z * sA;
    B  += blockIdx.z * sB;
    Cp += blockIdx.z * sC;
    int m0 = blockIdx.y * 64, n0 = blockIdx.x * 64;
    int tid = threadIdx.x;  // 256
    int tm = (tid / 16) * 4;
    int tn = (tid % 16) * 4;
    float acc[4][4] = {};
    for (int k0 = 0; k0 < K; k0 += 16) {
#pragma unroll
        for (int i = 0; i < 4; i++) {
            int idx = tid + i * 256;
            int am = idx / 16, ak = idx % 16;
            float v = 0.f;
            if (m0 + am < M && k0 + ak < K) v = A[(long long)(m0 + am) * lda + k0 + ak];
            As[ak][am] = v;
        }
#pragma unroll
        for (int i = 0; i < 4; i++) {
            int idx = tid + i * 256;
            if (!TRANSB) {
                int bk = idx / 64, bn = idx % 64;
                float v = 0.f;
                if (k0 + bk < K && n0 + bn < N) v = B[(long long)(k0 + bk) * ldb + n0 + bn];
                Bs[bk][bn] = v;
            } else {
                int bn = idx / 16, bk = idx % 16;
                float v = 0.f;
                if (k0 + bk < K && n0 + bn < N) v = B[(long long)(n0 + bn) * ldb + k0 + bk];
                Bs[bk][bn] = v;
            }
        }
        __syncthreads();
#pragma unroll
        for (int k = 0; k < 16; k++) {
            float a[4], b[4];
#pragma unroll
            for (int i = 0; i < 4; i++) a[i] = As[k][tm + i];
#pragma unroll
            for (int j = 0; j < 4; j++) b[j] = Bs[k][tn + j];
#pragma unroll
            for (int i = 0; i < 4; i++)
#pragma unroll
                for (int j = 0; j < 4; j++) acc[i][j] += a[i] * b[j];
        }
        __syncthreads();
    }
#pragma unroll
    for (int i = 0; i < 4; i++) {
        int m = m0 + tm + i;
        if (m >= M) continue;
#pragma unroll
        for (int j = 0; j < 4; j++) {
            int n = n0 + tn + j;
            if (n >= N) continue;
            Cp[(long long)m * ldc + n] = alpha * acc[i][j];
        }
    }
}

// -------- fast SGEMM core (128x128x8, 8x8 via f32x2, dbuf, conflict-free) ----
template <bool TRANSB>
__device__ __forceinline__ void sgemm128_core(
    const float* __restrict__ A, int lda,
    const float* __restrict__ B, int ldb,
    float* __restrict__ Cp, int ldc,
    int M, int N, float alpha, int m0, int n0, int kbeg, int kend) {
    __shared__ __align__(16) float Asd[2][8][264];  // [k][2*m] duplicated
    __shared__ __align__(16) float Bs[2][8][132];   // [k][n]
    const int tid = threadIdx.x;              // 256
    const int tx = tid & 15, ty = tid >> 4;
    const int arow = tid >> 1, ak4 = (tid & 1) * 4;   // A (and B if TRANSB) loads
    const int bk = tid >> 5, bn4 = (tid & 31) * 4;    // B loads if !TRANSB

    unsigned long long acc2[8][4] = {};  // 8 m-rows x 4 packed n-pairs

    if (kend > kbeg) {
        const int t0 = kbeg >> 3, t1 = kend >> 3;
        float4 ar, br;
        const float4 fz = make_float4(0.f, 0.f, 0.f, 0.f);

        ar = (m0 + arow < M) ? *(const float4*)(A + (long long)(m0 + arow) * lda + kbeg + ak4) : fz;
        if (TRANSB) {
            br = (n0 + arow < N) ? *(const float4*)(B + (long long)(n0 + arow) * ldb + kbeg + ak4) : fz;
        } else {
            if (n0 + bn4 + 3 < N) {
                br = *(const float4*)(B + (long long)(kbeg + bk) * ldb + n0 + bn4);
            } else {
                const float* Bp = B + (long long)(kbeg + bk) * ldb;
                br.x = (n0 + bn4 + 0 < N) ? Bp[n0 + bn4 + 0] : 0.f;
                br.y = (n0 + bn4 + 1 < N) ? Bp[n0 + bn4 + 1] : 0.f;
                br.z = (n0 + bn4 + 2 < N) ? Bp[n0 + bn4 + 2] : 0.f;
                br.w = (n0 + bn4 + 3 < N) ? Bp[n0 + bn4 + 3] : 0.f;
            }
        }
        *(float2*)&Asd[0][ak4 + 0][2 * arow] = make_float2(ar.x, ar.x);
        *(float2*)&Asd[0][ak4 + 1][2 * arow] = make_float2(ar.y, ar.y);
        *(float2*)&Asd[0][ak4 + 2][2 * arow] = make_float2(ar.z, ar.z);
        *(float2*)&Asd[0][ak4 + 3][2 * arow] = make_float2(ar.w, ar.w);
        if (TRANSB) {
            Bs[0][ak4 + 0][arow] = br.x; Bs[0][ak4 + 1][arow] = br.y;
            Bs[0][ak4 + 2][arow] = br.z; Bs[0][ak4 + 3][arow] = br.w;
        } else {
            *(float4*)&Bs[0][bk][bn4] = br;
        }
        __syncthreads();

        for (int t = t0; t < t1; t++) {
            const int buf = (t - t0) & 1;
            const int kn = (t + 1) << 3;
            if (t + 1 < t1) {
                ar = (m0 + arow < M) ? *(const float4*)(A + (long long)(m0 + arow) * lda + kn + ak4) : fz;
                if (TRANSB) {
                    br = (n0 + arow < N) ? *(const float4*)(B + (long long)(n0 + arow) * ldb + kn + ak4) : fz;
                } else {
                    if (n0 + bn4 + 3 < N) {
                        br = *(const float4*)(B + (long long)(kn + bk) * ldb + n0 + bn4);
                    } else {
                        const float* Bp = B + (long long)(kn + bk) * ldb;
                        br.x = (n0 + bn4 + 0 < N) ? Bp[n0 + bn4 + 0] : 0.f;
                        br.y = (n0 + bn4 + 1 < N) ? Bp[n0 + bn4 + 1] : 0.f;
                        br.z = (n0 + bn4 + 2 < N) ? Bp[n0 + bn4 + 2] : 0.f;
                        br.w = (n0 + bn4 + 3 < N) ? Bp[n0 + bn4 + 3] : 0.f;
                    }
                }
            }
#pragma unroll
            for (int k = 0; k < 8; k++) {
                unsigned long long a2[8], b2[4];
#pragma unroll
                for (int i = 0; i < 8; i++)
                    a2[i] = *(const unsigned long long*)&Asd[buf][k][(ty * 8 + i) * 2];
                float4 bf0 = *(const float4*)&Bs[buf][k][tx * 8];
                float4 bf1 = *(const float4*)&Bs[buf][k][tx * 8 + 4];
                b2[0] = pack2(bf0.x, bf0.y);
                b2[1] = pack2(bf0.z, bf0.w);
                b2[2] = pack2(bf1.x, bf1.y);
                b2[3] = pack2(bf1.z, bf1.w);
#pragma unroll
                for (int i = 0; i < 8; i++)
#pragma unroll
                    for (int j = 0; j < 4; j++) acc2[i][j] = ffma2(a2[i], b2[j], acc2[i][j]);
            }
            if (t + 1 < t1) {
                const int b2i = (t + 1 - t0) & 1;
                *(float2*)&Asd[b2i][ak4 + 0][2 * arow] = make_float2(ar.x, ar.x);
                *(float2*)&Asd[b2i][ak4 + 1][2 * arow] = make_float2(ar.y, ar.y);
                *(float2*)&Asd[b2i][ak4 + 2][2 * arow] = make_float2(ar.z, ar.z);
                *(float2*)&Asd[b2i][ak4 + 3][2 * arow] = make_float2(ar.w, ar.w);
                if (TRANSB) {
                    Bs[b2i][ak4 + 0][arow] = br.x; Bs[b2i][ak4 + 1][arow] = br.y;
                    Bs[b2i][ak4 + 2][arow] = br.z; Bs[b2i][ak4 + 3][arow] = br.w;
                } else {
                    *(float4*)&Bs[b2i][bk][bn4] = br;
                }
            }
            __syncthreads();
        }
    }

#pragma unroll
    for (int i = 0; i < 8; i++) {
        int m = m0 + ty * 8 + i;
        if (m >= M) continue;
        float* Cr = Cp + (long long)m * ldc;
#pragma unroll
        for (int j = 0; j < 4; j++) {
            int n = n0 + tx * 8 + 2 * j;
            float lo = __uint_as_float((unsigned int)acc2[i][j]);
            float hi = __uint_as_float((unsigned int)(acc2[i][j] >> 32));
            if (n < N)     Cr[n]     = alpha * lo;
            if (n + 1 < N) Cr[n + 1] = alpha * hi;
        }
    }
}

// -------------------- K-split wrapper: writes partial chunks -----------------
// blockIdx.z = pair * nsplit + chunk. Partial layout: [(pair*nsplit+chunk)][M*N].
template <bool TRANSB>
__global__ __launch_bounds__(256)
void sgemm128_split_kernel(const float* __restrict__ A, long long sA, int lda,
                           const float* __restrict__ B, long long sB, int ldb,
                           float* __restrict__ part,
                           int M, int N, int K, int nsplit, int kchunk,
                           int kbmode, int kemode) {
    int pair = blockIdx.z / nsplit;
    int chunk = blockIdx.z % nsplit;
    int m0 = blockIdx.y * 128, n0 = blockIdx.x * 128;
    int kb = chunk * kchunk;
    int ke = min(kb + kchunk, K);
    if (kbmode == 1) kb = max(kb, n0);
    if (kemode == 1) ke = min(ke, m0 + 128);
    float* Cp = part + (long long)blockIdx.z * M * N;
    sgemm128_core<TRANSB>(A + pair * sA, lda, B + pair * sB, ldb,
                          Cp, N, M, N, 1.0f, m0, n0, kb, ke);
}

// Fused T|G (stacked) = [W; query] @ Linv^T with K-split + lower-tri clipping.
__global__ __launch_bounds__(256)
void sgemm128_dual_split_kernel(const float* __restrict__ A1, int nby1,
                                const float* __restrict__ A2,
                                const float* __restrict__ B,
                                float* __restrict__ part, int kchunk) {
    int chunk = blockIdx.z;
    const float* A;
    int M, m0, rowoff;
    if ((int)blockIdx.y < nby1) {
        A = A1; M = NU; m0 = blockIdx.y * 128; rowoff = 0;
    } else {
        A = A2; M = Qq; m0 = (blockIdx.y - nby1) * 128; rowoff = NU;
    }
    int n0 = blockIdx.x * 128;
    int kb = chunk * kchunk;
    int ke = min(min(kb + kchunk, Dd), n0 + 128);   // Linv lower-tri
    float* Cp = part + (long long)chunk * NUQ * Dd + (long long)rowoff * Dd;
    sgemm128_core<true>(A, Dd, B, Dd, Cp, Dd, M, Dd, 1.0f, m0, n0, kb, ke);
}

// -------------------- reduce partial chunks into output ----------------------
__global__ void reduce_kernel(const float* __restrict__ part, float* __restrict__ out,
                              int nsplit, int M, int N, int ldc, long long sOut,
                              float alpha, int pairs) {
    long long idx = (long long)blockIdx.x * blockDim.x + threadIdx.x;
    long long total = (long long)pairs * M * N;
    if (idx >= total) return;
    int pair = (int)(idx / ((long long)M * N));
    long long rem = idx - (long long)pair * M * N;
    int mm = (int)(rem / N);
    int nn = (int)(rem - (long long)mm * N);
    const float* p = part + (long long)pair * nsplit * M * N + rem;
    float s = 0.f;
    for (int c = 0; c < nsplit; c++) s += p[(long long)c * M * N];
    out[pair * sOut + (long long)mm * ldc + nn] = alpha * s;
}

// ----------------- fused per-class means + W build ---------------------------
__global__ void build_WM_kernel(const float* __restrict__ support,
                                const float* __restrict__ m) {
    int idx = blockIdx.x * blockDim.x + threadIdx.x;  // over C * D
    if (idx >= Cc * Dd) return;
    int c = idx / Dd, d = idx % Dd;
    const int* so = g_sample_of + c * SHOTSn;
    float mv = m[d];
    float s = 0.f;
#pragma unroll 4
    for (int j = 0; j < SHOTSn; j++)
        s += support[(long long)so[j] * Dd + d];
    Cls cl = g_cls[c];
    float xbar = s / cl.Nj;
    float mu = (g_kappa_ * mv + s) / cl.kN;
    g_xbar[idx] = xbar;
    g_mu[idx] = mu;
    float* Wc = g_W + (long long)(c * KW) * Dd + d;
#pragma unroll 4
    for (int k = 0; k < SHOTSn; k++)
        Wc[(long long)k * Dd] = support[(long long)so[k] * Dd + d] - xbar;
    float c2 = sqrtf(g_kappa_ * cl.Nj / cl.kN);
    Wc[(long long)SHOTSn * Dd] = c2 * (xbar - mv);
    Wc[(long long)(SHOTSn + 1) * Dd] = mu;
}

// ---------------- all row norms in one launch (G, query, mu) -----------------
__global__ void rownorm_all_kernel(const float* __restrict__ G,
                                   const float* __restrict__ query) {
    int r = blockIdx.x, t = threadIdx.x;  // 256 threads
    const float* row;
    float* dst;
    if (r < Qq)            { row = G + (long long)r * Dd;            dst = g_Gn2 + r; }
    else if (r < 2 * Qq)   { row = query + (long long)(r - Qq) * Dd; dst = g_qn2 + (r - Qq); }
    else                   { row = g_mu + (long long)(r - 2 * Qq) * Dd; dst = g_mun2 + (r - 2 * Qq); }
    float s = 0.f;
    for (int j = t; j < Dd; j += blockDim.x) { float v = row[j]; s += v * v; }
    __shared__ float red[8];
    for (int o = 16; o > 0; o >>= 1) s += __shfl_down_sync(0xffffffffu, s, o);
    if ((t & 31) == 0) red[t >> 5] = s;
    __syncthreads();
    if (t < 32) {
        float v = (t < 8) ? red[t] : 0.f;
        for (int o = 4; o > 0; o >>= 1) v += __shfl_down_sync(0xffffffffu, v, o);
        if (t == 0) *dst = v;
    }
}

// ---------------- K-split Gram: TtT partials per (class, chunk) --------------
__global__ void gram_split_kernel(const float* __restrict__ T,
                                  float* __restrict__ part,
                                  int nsplit, int kchunk) {
    __shared__ __align__(16) float Ts[KW][256 + 4];
    int c = blockIdx.x / nsplit;
    int chunk = blockIdx.x % nsplit;
    int tid = threadIdx.x;  // 256
    const float* Tc = T + (long long)(c * KW) * Dd + chunk * kchunk;
    // cooperative load KW x kchunk (kchunk <= 256)
    for (int i = tid; i < KW * (kchunk / 4); i += blockDim.x) {
        int row = i / (kchunk / 4), k4 = (i % (kchunk / 4)) * 4;
        *(float4*)&Ts[row][k4] = *(const float4*)(Tc + (long long)row * Dd + k4);
    }
    __syncthreads();
    float* outp = part + (long long)blockIdx.x * KW * KW;
    for (int e = tid; e < KW * KW; e += blockDim.x) {
        int i = e / KW, j = e % KW;
        float s = 0.f;
        for (int k = 0; k < kchunk; k += 4) {
            float4 a = *(const float4*)&Ts[i][k];
            float4 b = *(const float4*)&Ts[j][k];
            s += a.x * b.x + a.y * b.y + a.z * b.z + a.w * b.w;
        }
        outp[e] = s;
    }
}

// -------- per-class SPD 33x33 inverse (fp64 Gauss-Jordan) + logdet/bias ------
__global__ void small_inv_kernel() {
    int c = blockIdx.x, t = threadIdx.x;  // 64 threads
    __shared__ double Ms[KV][KV + 1];
    __shared__ double Iv[KV][KV + 1];
    __shared__ double s_logdet;
    __shared__ int    s_piv;
    const float* TtT = g_TtT + c * KW * KW;
    for (int i = t; i < KV * KV; i += blockDim.x) {
        int r = i / KV, cc = i % KV;
        Ms[r][cc] = (double)TtT[r * KW + cc] + (r == cc ? 1.0 : 0.0);  // M = I + T T^T
        Iv[r][cc] = (r == cc) ? 1.0 : 0.0;
    }
    if (t < KV) g_b[c * KW + t] = TtT[t * KW + (KW - 1)];  // t_a . t_mu
    if (t == 0) s_logdet = 0.0;
    __syncthreads();
    for (int k = 0; k < KV; k++) {
        if (t == 0) {
            int p = k; double best = fabs(Ms[k][k]);
            for (int r = k + 1; r < KV; r++) {
                double a = fabs(Ms[r][k]);
                if (a > best) { best = a; p = r; }
            }
            s_piv = p;
        }
        __syncthreads();
        int p = s_piv;
        if (p != k && t < KV) {
            double tmp = Ms[k][t]; Ms[k][t] = Ms[p][t]; Ms[p][t] = tmp;
            tmp = Iv[k][t]; Iv[k][t] = Iv[p][t]; Iv[p][t] = tmp;
        }
        __syncthreads();
        double piv = Ms[k][k];
        if (t == 0) s_logdet += log(fabs(piv));
        double pivinv = 1.0 / piv;
        if (t < KV) { Ms[k][t] *= pivinv; Iv[k][t] *= pivinv; }
        __syncthreads();
        if (t < KV && t != k) {
            double f = Ms[t][k];
            for (int j = 0; j < KV; j++) {
                Ms[t][j] -= f * Ms[k][j];
                Iv[t][j] -= f * Iv[k][j];
            }
        }
        __syncthreads();
    }
    for (int i = t; i < KV * KV; i += blockDim.x)
        g_Kinv[c * KW * KW + i] = (float)Iv[i / KV][i % KV];
    if (t == 0) {
        Cls cl = g_cls[c];
        double logdetS = 2.0 * (double)g_sumlogL + s_logdet;
        double logdet_sigma = (double)Dd * log((double)cl.scale) + logdetS;
        double common_ = (double)cl.common_;
        double bias = lgamma(0.5 * (common_ + (double)Dd)) - lgamma(0.5 * common_)
                    - 0.5 * (double)Dd * log(common_) - 0.5 * logdet_sigma;
        g_cls[c].bias = (float)bias;
        g_cls[c].hh = TtT[(KW - 1) * KW + (KW - 1)];  // ||t_mu||^2
    }
}

// --------------------------------- finalize ----------------------------------
__global__ void finalize_kernel(float* __restrict__ out) {
    int c = blockIdx.y;
    int q = blockIdx.x * blockDim.x + threadIdx.x;
    __shared__ float Ks[KV * KV];
    __shared__ float bs[KV];
    __shared__ Cls cl;
    for (int i = threadIdx.x; i < KV * KV; i += blockDim.x) Ks[i] = g_Kinv[c * KW * KW + i];
    if (threadIdx.x < KV) bs[threadIdx.x] = g_b[c * KW + threadIdx.x];
    if (threadIdx.x == 0) cl = g_cls[c];
    __syncthreads();
    if (q >= Qq) return;
    const float* Ur = g_U + (long long)q * NU + c * KW;
    float v[KV];
    float u33 = Ur[KW - 1];  // g . t_mu
#pragma unroll
    for (int i = 0; i < KV; i++) v[i] = Ur[i] - bs[i];  // u_a = t_a.(g - t_mu)
    float s = 0.f;
#pragma unroll 4
    for (int i = 0; i < KV; i++) {
        float acc = 0.f;
#pragma unroll
        for (int j = 0; j < KV; j++) acc += Ks[i * KV + j] * v[j];
        s += v[i] * acc;
    }
    float distA = g_Gn2[q] - 2.0f * u33 + cl.hh - s;
    float dist  = cl.invscale_half * distA
                + 0.5f * (g_qn2[q] - 2.0f * g_qm[q * Cc + c] + g_mun2[c]);
    out[(long long)q * Cc + c] = cl.bias - cl.coefD * log1pf(dist * cl.inv_common);
}

// ------------------------------ host launchers -------------------------------
static void sgemm_small(const float* A, long long sA, int lda,
                        const float* B, long long sB, int ldb,
                        float* Cmat, long long sC, int ldc,
                        int M, int N, int K, float alpha, bool transB, int batch) {
    dim3 grid((N + 63) / 64, (M + 63) / 64, batch);
    if (transB)
        sgemm_kernel<true><<<grid, 256>>>(A, sA, lda, B, sB, ldb, Cmat, sC, ldc, M, N, K, alpha);
    else
        sgemm_kernel<false><<<grid, 256>>>(A, sA, lda, B, sB, ldb, Cmat, sC, ldc, M, N, K, alpha);
}

static void sgemm_big_split(const float* A, long long sA, int lda,
                            const float* B, long long sB, int ldb,
                            float* part, float* out, long long sOut, int ldc,
                            int M, int N, int K, float alpha, bool transB, int pairs,
                            int nsplit, int kchunk, int kbmode, int kemode) {
    dim3 grid((N + 127) / 128, (M + 127) / 128, pairs * nsplit);
    if (transB)
        sgemm128_split_kernel<true><<<grid, 256>>>(A, sA, lda, B, sB, ldb, part,
                                                   M, N, K, nsplit, kchunk, kbmode, kemode);
    else
        sgemm128_split_kernel<false><<<grid, 256>>>(A, sA, lda, B, sB, ldb, part,
                                                    M, N, K, nsplit, kchunk, kbmode, kemode);
    long long total = (long long)pairs * M * N;
    reduce_kernel<<<(unsigned)((total + 255) / 256), 256>>>(part, out, nsplit, M, N, ldc,
                                                            sOut, alpha, pairs);
}

extern "C" void kernel_launch(void* const* d_in, const int* in_sizes, int n_in,
                              void* d_out, int out_size) {
    const float* support = (const float*)d_in[0];
    const float* query   = (const float*)d_in[1];
    const int*   labels  = (const int*)d_in[2];
    const float* m       = (const float*)d_in[3];
    const float* kappa   = (const float*)d_in[4];
    const float* nu      = (const float*)d_in[5];
    const float* tdiag   = (const float*)d_in[6];
    const float* tlower  = (const float*)d_in[7];
    float* out = (float*)d_out;

    float *pL, *pLinv, *pTmp, *pW, *pTG, *pU, *pPart, *pTtT, *pMu, *pQm;
    cudaGetSymbolAddress((void**)&pL, g_L);
    cudaGetSymbolAddress((void**)&pLinv, g_Linv);
    cudaGetSymbolAddress((void**)&pTmp, g_Tmp);
    cudaGetSymbolAddress((void**)&pW, g_W);
    cudaGetSymbolAddress((void**)&pTG, g_TG);
    cudaGetSymbolAddress((void**)&pU, g_U);
    cudaGetSymbolAddress((void**)&pPart, g_Part);
    cudaGetSymbolAddress((void**)&pTtT, g_TtT);
    cudaGetSymbolAddress((void**)&pMu, g_mu);
    cudaGetSymbolAddress((void**)&pQm, g_qm);
    float* pT = pTG;                        // T: rows 0..NU-1
    float* pG = pTG + (long long)NU * Dd;   // G: rows NU..NU+Qq-1

    // 1) scalars, per-class params, stable sample gather, sum log|diag L|
    setup_kernel<<<1, NSUP>>>(labels, kappa, nu, tdiag);

    // 2) fused per-class xbar/mu + W = [X_c - xbar | sqrt(.)*(xbar-m) | mu_c]
    build_WM_kernel<<<(Cc * Dd + 255) / 256, 256>>>(support, m);

    // 3) L and L^{-1} (recursive-doubling blocked triangular inverse)
    build_L_kernel<<<(Dd * Dd + 255) / 256, 256>>>(tdiag, tlower);
    inv_diag_kernel<<<32, 32>>>();
    for (int lev = 1; lev <= 2; lev++) {   // s = 32, 64
        int s = 32 << (lev - 1);
        int pairs = 32 >> lev;
        long long stride = 2LL * s * (Dd + 1);
        sgemm_small(pL + (long long)s * Dd, stride, Dd,
                    pLinv, stride, Dd,
                    pTmp, (long long)s * s, s,
                    s, s, s, 1.0f, false, pairs);
        sgemm_small(pLinv + (long long)s * Dd + s, stride, Dd,
                    pTmp, (long long)s * s, s,
                    pLinv + (long long)s * Dd, stride, Dd,
                    s, s, s, -1.0f, false, pairs);
    }
    for (int lev = 3; lev <= 5; lev++) {   // s = 128, 256, 512: K-split fast core
        int s = 32 << (lev - 1);
        int pairs = 32 >> lev;
        long long stride = 2LL * s * (Dd + 1);
        int nsplit = (s == 128) ? 2 : ((s == 256) ? 4 : 8);
        int kchunk = s / nsplit;  // 64 each
        sgemm_big_split(pL + (long long)s * Dd, stride, Dd,
                        pLinv, stride, Dd,
                        pPart, pTmp, (long long)s * s, s,
                        s, s, s, 1.0f, false, pairs, nsplit, kchunk, 1, 0);
        sgemm_big_split(pLinv + (long long)s * Dd + s, stride, Dd,
                        pTmp, (long long)s * s, s,
                        pPart, pLinv + (long long)s * Dd, stride, Dd,
                        s, s, s, -1.0f, false, pairs, nsplit, kchunk, 0, 1);
    }

    // 4+5) fused K-split: [T; G] = [W; query] @ Linv^T  (stacked 2112 x 1024)
    {
        int nby1 = (NU + 127) / 128;       // 9
        int nby2 = (Qq + 127) / 128;       // 8
        dim3 grid(Dd / 128, nby1 + nby2, 2);  // (8, 17, 2)
        sgemm128_dual_split_kernel<<<grid, 256>>>(pW, nby1, query, pLinv, pPart, Dd / 2);
        long long total = (long long)NUQ * Dd;
        reduce_kernel<<<(unsigned)((total + 255) / 256), 256>>>(pPart, pTG, 2, NUQ, Dd, Dd,
                                                                0, 1.0f, 1);
    }

    // 6) all row norms in one launch: ||L^{-1}q||^2, ||q||^2, ||mu||^2
    rownorm_all_kernel<<<2 * Qq + Cc, 256>>>(pG, query);

    // 7) TtT per class via K-split Gram + reduce; then fp64 33x33 inverse
    gram_split_kernel<<<Cc * 4, 256>>>(pT, pPart, 4, Dd / 4);
    {
        long long total = (long long)Cc * KW * KW;
        reduce_kernel<<<(unsigned)((total + 255) / 256), 256>>>(pPart, pTtT, 4, KW, KW, KW,
                                                                (long long)KW * KW, 1.0f, Cc);
    }
    small_inv_kernel<<<Cc, 64>>>();

    // 8) U = G @ T^T  [1024 x 1088]  K-split x4
    sgemm_big_split(pG, 0, Dd, pT, 0, Dd,
                    pPart, pU, 0, NU,
                    Qq, NU, Dd, 1.0f, true, 1, 4, Dd / 4, 0, 0);

    // 9) qm = query @ mu^T  [Q x C]  via fast core, K-split x4
    sgemm_big_split(query, 0, Dd, pMu, 0, Dd,
                    pPart, pQm, 0, Cc,
                    Qq, Cc, Dd, 1.0f, true, 1, 4, Dd / 4, 0, 0);

    // 10) fuse quadratic forms + bias + log1p
    finalize_kernel<<<dim3((Qq + 127) / 128, Cc), 128>>>(out);
}

// round 12
// speedup vs baseline: 1.5305x; 1.0339x over previous
#include <cuda_runtime.h>
#include <math.h>

// ---------------------------------------------------------------------------
// MetaQDA via conditioned Woodbury / matrix-determinant-lemma restructuring.
//   S_c = L L^T + V_c^T V_c,   V_c = [x_i - xbar (32 rows); sqrt(kappa*N/kN)(xbar - m)]
//   S^{-1} = L^{-T}(I - T^T M^{-1} T)L^{-1},  T = V L^{-T} (33 x D),  M = I + T T^T (SPD)
//   logdet S = 2 sum log|L_ii| + logdet M
// GEMM core: 128x128x8 double-buffered, packed fma.rn.f32x2, conflict-free.
// trtri: 64x64 register-resident diag inverse + combine levels s=64,128,256,512
// (the s=64 level was missing in R10 -> wrong off-diagonal L^{-1} blocks).
// ---------------------------------------------------------------------------

#define Dd   1024
#define Cc   32
#define SHOTSn 32
#define NSUP 1024
#define Qq   1024
#define KW   34     // rows of T-hat per class: 32 centered + scaled-diff + mu(aux)
#define KV   33     // rows entering the Woodbury capacitance M
#define NU   (Cc * KW)   // 1088
#define NUQ  (NU + Qq)   // 2112

// ------------------------- scratch (device globals) -------------------------
__device__ float g_L[Dd * Dd];
__device__ float g_Linv[Dd * Dd];
__device__ float g_Tmp[512 * 512];
__device__ float g_W[NU * Dd];
__device__ float g_TG[NUQ * Dd];        // T (first NU rows) then G (Qq rows)
__device__ float g_U[Qq * NU];          // [q][c*KW + k]
__device__ float g_Part[4 * NUQ * Dd];  // K-split partial buffer
__device__ float g_TtT[Cc * KW * KW];
__device__ float g_Kinv[Cc * KW * KW];  // packed KV x KV per class
__device__ float g_b[Cc * KW];
__device__ float g_mu[Cc * Dd];
__device__ float g_xbar[Cc * Dd];
__device__ float g_Gn2[Qq];
__device__ float g_qn2[Qq];
__device__ float g_mun2[Cc];
__device__ float g_qm[Qq * Cc];
__device__ int   g_sample_of[Cc * SHOTSn];

struct Cls {
    float Nj, kN, common_, scale;
    float bias, coefD, inv_common, invscale_half, hh;
};
__device__ Cls   g_cls[Cc];
__device__ float g_kappa_;
__device__ float g_sumlogL;

// ------------------------------ f32x2 helpers --------------------------------
__device__ __forceinline__ unsigned long long ffma2(unsigned long long a,
                                                    unsigned long long b,
                                                    unsigned long long c) {
    unsigned long long d;
    asm("fma.rn.f32x2 %0, %1, %2, %3;" : "=l"(d) : "l"(a), "l"(b), "l"(c));
    return d;
}
__device__ __forceinline__ unsigned long long pack2(float lo, float hi) {
    unsigned long long r;
    asm("mov.b64 %0, {%1, %2};" : "=l"(r) : "f"(lo), "f"(hi));
    return r;
}

// ------------------------------- setup --------------------------------------
// Parallel within-class ranking: __match_any intra-warp rank + per-warp
// histogram prefix. Bit-identical ordering to a serial scan.
__global__ void setup_kernel(const int* __restrict__ labels,
                             const float* __restrict__ kappa_p,
                             const float* __restrict__ nu_p,
                             const float* __restrict__ triu_diag) {
    __shared__ int   hist[32][33];   // [warp][class]
    __shared__ float red[32];
    int t = threadIdx.x;  // 1024 threads
    int w = t >> 5, lane = t & 31;
    hist[w][lane] = 0;
    g_sample_of[t] = 0;
    __syncthreads();

    int l = labels[t];
    unsigned mask = __match_any_sync(0xffffffffu, l);
    int intra = __popc(mask & ((1u << lane) - 1u));
    int leader = __ffs(mask) - 1;
    if (lane == leader && l >= 0 && l < Cc) hist[w][l] = __popc(mask);
    __syncthreads();
    if (l >= 0 && l < Cc) {
        int cnt = intra;
        for (int w2 = 0; w2 < w; w2++) cnt += hist[w2][l];
        if (cnt < SHOTSn) g_sample_of[l * SHOTSn + cnt] = t;
    }

    // sum log |diag L|
    float v = logf(fabsf(triu_diag[t]));
    for (int o = 16; o > 0; o >>= 1) v += __shfl_down_sync(0xffffffffu, v, o);
    if (lane == 0) red[w] = v;
    __syncthreads();
    if (t < 32) {
        float s = red[t];
        for (int o = 16; o > 0; o >>= 1) s += __shfl_down_sync(0xffffffffu, s, o);
        if (t == 0) g_sumlogL = s;
    }

    if (t < Cc) {
        int nj = 0;
        for (int w2 = 0; w2 < 32; w2++) nj += hist[w2][t];
        float kappa_ = fabsf(*kappa_p) + 1e-6f;
        float nu_    = fmaxf(*nu_p, (float)(Dd - 1) + 1e-6f);
        float Njf = (float)nj;
        float kN = kappa_ + Njf;
        float common_ = nu_ + Njf + 1.0f - (float)Dd;
        float scale = (kN + 1.0f) / (common_ * kN);
        Cls c;
        c.Nj = Njf; c.kN = kN; c.common_ = common_; c.scale = scale;
        c.bias = 0.f;
        c.coefD = 0.5f * (common_ + (float)Dd);
        c.inv_common = 1.0f / common_;
        c.invscale_half = 0.5f / scale;
        c.hh = 0.f;
        g_cls[t] = c;
        if (t == 0) g_kappa_ = kappa_;
    }
}

// --------------------------- build L (and zero Linv) -------------------------
__global__ void build_L_kernel(const float* __restrict__ tdiag,
                               const float* __restrict__ tlower) {
    int idx = blockIdx.x * blockDim.x + threadIdx.x;
    if (idx >= Dd * Dd) return;
    int i = idx / Dd, j = idx % Dd;
    float v = (i == j) ? fabsf(tdiag[i]) : (i > j ? tlower[idx] : 0.0f);
    g_L[idx] = v;
    g_Linv[idx] = 0.0f;
}

// --------- invert 64x64 lower-triangular diagonal blocks (registers) ---------
// Thread t owns column t; its solution vector lives in registers (full unroll).
// Ls reads are identical across threads -> smem broadcast, conflict-free.
__global__ void inv_diag64_kernel() {
    __shared__ float Ls[64][65];
    __shared__ float rd[64];
    int b = blockIdx.x, t = threadIdx.x;  // 64 threads
    int off = b * 64;
    for (int i = 0; i < 64; i++) Ls[i][t] = g_L[(long long)(off + i) * Dd + off + t];
    __syncthreads();
    rd[t] = 1.0f / Ls[t][t];
    __syncthreads();
    float x[64];
#pragma unroll
    for (int i = 0; i < 64; i++) {
        float s = (t == i) ? 1.0f : 0.0f;
#pragma unroll
        for (int k = 0; k < i; k++) s -= Ls[i][k] * x[k];
        x[i] = s * rd[i];
    }
#pragma unroll
    for (int i = 0; i < 64; i++)
        g_Linv[(long long)(off + i) * Dd + off + t] = x[i];
}

// -------- fast SGEMM core (128x128x8, 8x8 via f32x2, dbuf, conflict-free) ----
template <bool TRANSB>
__device__ __forceinline__ void sgemm128_core(
    const float* __restrict__ A, int lda,
    const float* __restrict__ B, int ldb,
    float* __restrict__ Cp, int ldc,
    int M, int N, float alpha, int m0, int n0, int kbeg, int kend) {
    __shared__ __align__(16) float Asd[2][8][264];  // [k][2*m] duplicated
    __shared__ __align__(16) float Bs[2][8][132];   // [k][n]
    const int tid = threadIdx.x;              // 256
    const int tx = tid & 15, ty = tid >> 4;
    const int arow = tid >> 1, ak4 = (tid & 1) * 4;   // A (and B if TRANSB) loads
    const int bk = tid >> 5, bn4 = (tid & 31) * 4;    // B loads if !TRANSB

    unsigned long long acc2[8][4] = {};  // 8 m-rows x 4 packed n-pairs

    if (kend > kbeg) {
        const int t0 = kbeg >> 3, t1 = kend >> 3;
        float4 ar, br;
        const float4 fz = make_float4(0.f, 0.f, 0.f, 0.f);

        ar = (m0 + arow < M) ? *(const float4*)(A + (long long)(m0 + arow) * lda + kbeg + ak4) : fz;
        if (TRANSB) {
            br = (n0 + arow < N) ? *(const float4*)(B + (long long)(n0 + arow) * ldb + kbeg + ak4) : fz;
        } else {
            if (n0 + bn4 + 3 < N) {
                br = *(const float4*)(B + (long long)(kbeg + bk) * ldb + n0 + bn4);
            } else {
                const float* Bp = B + (long long)(kbeg + bk) * ldb;
                br.x = (n0 + bn4 + 0 < N) ? Bp[n0 + bn4 + 0] : 0.f;
                br.y = (n0 + bn4 + 1 < N) ? Bp[n0 + bn4 + 1] : 0.f;
                br.z = (n0 + bn4 + 2 < N) ? Bp[n0 + bn4 + 2] : 0.f;
                br.w = (n0 + bn4 + 3 < N) ? Bp[n0 + bn4 + 3] : 0.f;
            }
        }
        *(float2*)&Asd[0][ak4 + 0][2 * arow] = make_float2(ar.x, ar.x);
        *(float2*)&Asd[0][ak4 + 1][2 * arow] = make_float2(ar.y, ar.y);
        *(float2*)&Asd[0][ak4 + 2][2 * arow] = make_float2(ar.z, ar.z);
        *(float2*)&Asd[0][ak4 + 3][2 * arow] = make_float2(ar.w, ar.w);
        if (TRANSB) {
            Bs[0][ak4 + 0][arow] = br.x; Bs[0][ak4 + 1][arow] = br.y;
            Bs[0][ak4 + 2][arow] = br.z; Bs[0][ak4 + 3][arow] = br.w;
        } else {
            *(float4*)&Bs[0][bk][bn4] = br;
        }
        __syncthreads();

        for (int t = t0; t < t1; t++) {
            const int buf = (t - t0) & 1;
            const int kn = (t + 1) << 3;
            if (t + 1 < t1) {
                ar = (m0 + arow < M) ? *(const float4*)(A + (long long)(m0 + arow) * lda + kn + ak4) : fz;
                if (TRANSB) {
                    br = (n0 + arow < N) ? *(const float4*)(B + (long long)(n0 + arow) * ldb + kn + ak4) : fz;
                } else {
                    if (n0 + bn4 + 3 < N) {
                        br = *(const float4*)(B + (long long)(kn + bk) * ldb + n0 + bn4);
                    } else {
                        const float* Bp = B + (long long)(kn + bk) * ldb;
                        br.x = (n0 + bn4 + 0 < N) ? Bp[n0 + bn4 + 0] : 0.f;
                        br.y = (n0 + bn4 + 1 < N) ? Bp[n0 + bn4 + 1] : 0.f;
                        br.z = (n0 + bn4 + 2 < N) ? Bp[n0 + bn4 + 2] : 0.f;
                        br.w = (n0 + bn4 + 3 < N) ? Bp[n0 + bn4 + 3] : 0.f;
                    }
                }
            }
#pragma unroll
            for (int k = 0; k < 8; k++) {
                unsigned long long a2[8], b2[4];
#pragma unroll
                for (int i = 0; i < 8; i++)
                    a2[i] = *(const unsigned long long*)&Asd[buf][k][(ty * 8 + i) * 2];
                float4 bf0 = *(const float4*)&Bs[buf][k][tx * 8];
                float4 bf1 = *(const float4*)&Bs[buf][k][tx * 8 + 4];
                b2[0] = pack2(bf0.x, bf0.y);
                b2[1] = pack2(bf0.z, bf0.w);
                b2[2] = pack2(bf1.x, bf1.y);
                b2[3] = pack2(bf1.z, bf1.w);
#pragma unroll
                for (int i = 0; i < 8; i++)
#pragma unroll
                    for (int j = 0; j < 4; j++) acc2[i][j] = ffma2(a2[i], b2[j], acc2[i][j]);
            }
            if (t + 1 < t1) {
                const int b2i = (t + 1 - t0) & 1;
                *(float2*)&Asd[b2i][ak4 + 0][2 * arow] = make_float2(ar.x, ar.x);
                *(float2*)&Asd[b2i][ak4 + 1][2 * arow] = make_float2(ar.y, ar.y);
                *(float2*)&Asd[b2i][ak4 + 2][2 * arow] = make_float2(ar.z, ar.z);
                *(float2*)&Asd[b2i][ak4 + 3][2 * arow] = make_float2(ar.w, ar.w);
                if (TRANSB) {
                    Bs[b2i][ak4 + 0][arow] = br.x; Bs[b2i][ak4 + 1][arow] = br.y;
                    Bs[b2i][ak4 + 2][arow] = br.z; Bs[b2i][ak4 + 3][arow] = br.w;
                } else {
                    *(float4*)&Bs[b2i][bk][bn4] = br;
                }
            }
            __syncthreads();
        }
    }

#pragma unroll
    for (int i = 0; i < 8; i++) {
        int m = m0 + ty * 8 + i;
        if (m >= M) continue;
        float* Cr = Cp + (long long)m * ldc;
#pragma unroll
        for (int j = 0; j < 4; j++) {
            int n = n0 + tx * 8 + 2 * j;
            float lo = __uint_as_float((unsigned int)acc2[i][j]);
            float hi = __uint_as_float((unsigned int)(acc2[i][j] >> 32));
            if (n < N)     Cr[n]     = alpha * lo;
            if (n + 1 < N) Cr[n + 1] = alpha * hi;
        }
    }
}

// -------------------- K-split wrapper: writes partial chunks -----------------
template <bool TRANSB>
__global__ __launch_bounds__(256)
void sgemm128_split_kernel(const float* __restrict__ A, long long sA, int lda,
                           const float* __restrict__ B, long long sB, int ldb,
                           float* __restrict__ part,
                           int M, int N, int K, int nsplit, int kchunk,
                           int kbmode, int kemode) {
    int pair = blockIdx.z / nsplit;
    int chunk = blockIdx.z % nsplit;
    int m0 = blockIdx.y * 128, n0 = blockIdx.x * 128;
    int kb = chunk * kchunk;
    int ke = min(kb + kchunk, K);
    if (kbmode == 1) kb = max(kb, n0);
    if (kemode == 1) ke = min(ke, m0 + 128);
    float* Cp = part + (long long)blockIdx.z * M * N;
    sgemm128_core<TRANSB>(A + pair * sA, lda, B + pair * sB, ldb,
                          Cp, N, M, N, 1.0f, m0, n0, kb, ke);
}

// -------------------- direct (no-split) wrapper ------------------------------
template <bool TRANSB>
__global__ __launch_bounds__(256)
void sgemm128_direct_kernel(const float* __restrict__ A, long long sA, int lda,
                            const float* __restrict__ B, long long sB, int ldb,
                            float* __restrict__ Cp, long long sC, int ldc,
                            int M, int N, int K, float alpha, int kbmode, int kemode) {
    int m0 = blockIdx.y * 128, n0 = blockIdx.x * 128;
    int kb = (kbmode == 1) ? n0 : 0;
    int ke = (kemode == 1) ? min(K, m0 + 128) : K;
    sgemm128_core<TRANSB>(A + blockIdx.z * sA, lda, B + blockIdx.z * sB, ldb,
                          Cp + blockIdx.z * sC, ldc, M, N, alpha, m0, n0, kb, ke);
}

// Fused T|G (stacked) = [W; query] @ Linv^T with K-split + lower-tri clipping.
__global__ __launch_bounds__(256)
void sgemm128_dual_split_kernel(const float* __restrict__ A1, int nby1,
                                const float* __restrict__ A2,
                                const float* __restrict__ B,
                                float* __restrict__ part, int kchunk) {
    int chunk = blockIdx.z;
    const float* A;
    int M, m0, rowoff;
    if ((int)blockIdx.y < nby1) {
        A = A1; M = NU; m0 = blockIdx.y * 128; rowoff = 0;
    } else {
        A = A2; M = Qq; m0 = (blockIdx.y - nby1) * 128; rowoff = NU;
    }
    int n0 = blockIdx.x * 128;
    int kb = chunk * kchunk;
    int ke = min(min(kb + kchunk, Dd), n0 + 128);   // Linv lower-tri
    float* Cp = part + (long long)chunk * NUQ * Dd + (long long)rowoff * Dd;
    sgemm128_core<true>(A, Dd, B, Dd, Cp, Dd, M, Dd, 1.0f, m0, n0, kb, ke);
}

// -------------------- reduce partial chunks into output ----------------------
__global__ void reduce_kernel(const float* __restrict__ part, float* __restrict__ out,
                              int nsplit, int M, int N, int ldc, long long sOut,
                              float alpha, int pairs) {
    long long idx = (long long)blockIdx.x * blockDim.x + threadIdx.x;
    long long total = (long long)pairs * M * N;
    if (idx >= total) return;
    int pair = (int)(idx / ((long long)M * N));
    long long rem = idx - (long long)pair * M * N;
    int mm = (int)(rem / N);
    int nn = (int)(rem - (long long)mm * N);
    const float* p = part + (long long)pair * nsplit * M * N + rem;
    float s = 0.f;
    for (int c = 0; c < nsplit; c++) s += p[(long long)c * M * N];
    out[pair * sOut + (long long)mm * ldc + nn] = alpha * s;
}

// ----------------- fused per-class means + W build ---------------------------
__global__ void build_WM_kernel(const float* __restrict__ support,
                                const float* __restrict__ m) {
    int idx = blockIdx.x * blockDim.x + threadIdx.x;  // over C * D
    if (idx >= Cc * Dd) return;
    int c = idx / Dd, d = idx % Dd;
    const int* so = g_sample_of + c * SHOTSn;
    float mv = m[d];
    float s = 0.f;
#pragma unroll 4
    for (int j = 0; j < SHOTSn; j++)
        s += support[(long long)so[j] * Dd + d];
    Cls cl = g_cls[c];
    float xbar = s / cl.Nj;
    float mu = (g_kappa_ * mv + s) / cl.kN;
    g_xbar[idx] = xbar;
    g_mu[idx] = mu;
    float* Wc = g_W + (long long)(c * KW) * Dd + d;
#pragma unroll 4
    for (int k = 0; k < SHOTSn; k++)
        Wc[(long long)k * Dd] = support[(long long)so[k] * Dd + d] - xbar;
    float c2 = sqrtf(g_kappa_ * cl.Nj / cl.kN);
    Wc[(long long)SHOTSn * Dd] = c2 * (xbar - mv);
    Wc[(long long)(SHOTSn + 1) * Dd] = mu;
}

// ---------------- all row norms in one launch (G, query, mu) -----------------
__global__ void rownorm_all_kernel(const float* __restrict__ G,
                                   const float* __restrict__ query) {
    int r = blockIdx.x, t = threadIdx.x;  // 256 threads
    const float* row;
    float* dst;
    if (r < Qq)            { row = G + (long long)r * Dd;            dst = g_Gn2 + r; }
    else if (r < 2 * Qq)   { row = query + (long long)(r - Qq) * Dd; dst = g_qn2 + (r - Qq); }
    else                   { row = g_mu + (long long)(r - 2 * Qq) * Dd; dst = g_mun2 + (r - 2 * Qq); }
    float s = 0.f;
    for (int j = t; j < Dd; j += blockDim.x) { float v = row[j]; s += v * v; }
    __shared__ float red[8];
    for (int o = 16; o > 0; o >>= 1) s += __shfl_down_sync(0xffffffffu, s, o);
    if ((t & 31) == 0) red[t >> 5] = s;
    __syncthreads();
    if (t < 32) {
        float v = (t < 8) ? red[t] : 0.f;
        for (int o = 4; o > 0; o >>= 1) v += __shfl_down_sync(0xffffffffu, v, o);
        if (t == 0) *dst = v;
    }
}

// ---------------- K-split Gram: TtT partials per (class, chunk) --------------
__global__ void gram_split_kernel(const float* __restrict__ T,
                                  float* __restrict__ part,
                                  int nsplit, int kchunk) {
    __shared__ __align__(16) float Ts[KW][256 + 4];
    int c = blockIdx.x / nsplit;
    int chunk = blockIdx.x % nsplit;
    int tid = threadIdx.x;  // 256
    const float* Tc = T + (long long)(c * KW) * Dd + chunk * kchunk;
    for (int i = tid; i < KW * (kchunk / 4); i += blockDim.x) {
        int row = i / (kchunk / 4), k4 = (i % (kchunk / 4)) * 4;
        *(float4*)&Ts[row][k4] = *(const float4*)(Tc + (long long)row * Dd + k4);
    }
    __syncthreads();
    float* outp = part + (long long)blockIdx.x * KW * KW;
    for (int e = tid; e < KW * KW; e += blockDim.x) {
        int i = e / KW, j = e % KW;
        float s = 0.f;
        for (int k = 0; k < kchunk; k += 4) {
            float4 a = *(const float4*)&Ts[i][k];
            float4 b = *(const float4*)&Ts[j][k];
            s += a.x * b.x + a.y * b.y + a.z * b.z + a.w * b.w;
        }
        outp[e] = s;
    }
}

// ------------------------- skinny qm = query @ mu^T --------------------------
// mus row stride 68 floats = 272 B (16B-aligned for float4); within an 8-lane
// LDS.128 phase, banks (4c+k) + 4 words/lane tile all 32 banks: conflict-free.
__global__ void qm_kernel(const float* __restrict__ query) {
    __shared__ __align__(16) float mus[32][68];
    int tid = threadIdx.x;  // 256
    int c = tid & 31, qi = tid >> 5;  // 8 q per block
    int q = blockIdx.x * 8 + qi;
    float acc = 0.f;
    for (int k0 = 0; k0 < Dd; k0 += 64) {
        for (int i = tid; i < 32 * 16; i += 256) {
            int row = i / 16, k4 = (i % 16) * 4;
            *(float4*)&mus[row][k4] = *(const float4*)(g_mu + (long long)row * Dd + k0 + k4);
        }
        __syncthreads();
        const float* qr = query + (long long)q * Dd + k0;
#pragma unroll
        for (int k = 0; k < 64; k += 4) {
            float4 qv = *(const float4*)(qr + k);     // broadcast across warp
            float4 mv = *(const float4*)&mus[c][k];
            acc += qv.x * mv.x + qv.y * mv.y + qv.z * mv.z + qv.w * mv.w;
        }
        __syncthreads();
    }
    g_qm[(long long)q * Cc + c] = acc;
}

// -------- per-class SPD 33x33 inverse (fp64 Gauss-Jordan) + logdet/bias ------
__global__ void small_inv_kernel() {
    int c = blockIdx.x, t = threadIdx.x;  // 64 threads
    __shared__ double Ms[KV][KV + 1];
    __shared__ double Iv[KV][KV + 1];
    __shared__ double s_logdet;
    __shared__ int    s_piv;
    const float* TtT = g_TtT + c * KW * KW;
    for (int i = t; i < KV * KV; i += blockDim.x) {
        int r = i / KV, cc = i % KV;
        Ms[r][cc] = (double)TtT[r * KW + cc] + (r == cc ? 1.0 : 0.0);  // M = I + T T^T
        Iv[r][cc] = (r == cc) ? 1.0 : 0.0;
    }
    if (t < KV) g_b[c * KW + t] = TtT[t * KW + (KW - 1)];  // t_a . t_mu
    if (t == 0) s_logdet = 0.0;
    __syncthreads();
    for (int k = 0; k < KV; k++) {
        if (t == 0) {
            int p = k; double best = fabs(Ms[k][k]);
            for (int r = k + 1; r < KV; r++) {
                double a = fabs(Ms[r][k]);
                if (a > best) { best = a; p = r; }
            }
            s_piv = p;
        }
        __syncthreads();
        int p = s_piv;
        if (p != k && t < KV) {
            double tmp = Ms[k][t]; Ms[k][t] = Ms[p][t]; Ms[p][t] = tmp;
            tmp = Iv[k][t]; Iv[k][t] = Iv[p][t]; Iv[p][t] = tmp;
        }
        __syncthreads();
        double piv = Ms[k][k];
        if (t == 0) s_logdet += log(fabs(piv));
        double pivinv = 1.0 / piv;
        if (t < KV) { Ms[k][t] *= pivinv; Iv[k][t] *= pivinv; }
        __syncthreads();
        if (t < KV && t != k) {
            double f = Ms[t][k];
            for (int j = 0; j < KV; j++) {
                Ms[t][j] -= f * Ms[k][j];
                Iv[t][j] -= f * Iv[k][j];
            }
        }
        __syncthreads();
    }
    for (int i = t; i < KV * KV; i += blockDim.x)
        g_Kinv[c * KW * KW + i] = (float)Iv[i / KV][i % KV];
    if (t == 0) {
        Cls cl = g_cls[c];
        double logdetS = 2.0 * (double)g_sumlogL + s_logdet;
        double logdet_sigma = (double)Dd * log((double)cl.scale) + logdetS;
        double common_ = (double)cl.common_;
        double bias = lgamma(0.5 * (common_ + (double)Dd)) - lgamma(0.5 * common_)
                    - 0.5 * (double)Dd * log(common_) - 0.5 * logdet_sigma;
        g_cls[c].bias = (float)bias;
        g_cls[c].hh = TtT[(KW - 1) * KW + (KW - 1)];  // ||t_mu||^2
    }
}

// --------------------------------- finalize ----------------------------------
__global__ void finalize_kernel(float* __restrict__ out) {
    int c = blockIdx.y;
    int q = blockIdx.x * blockDim.x + threadIdx.x;
    __shared__ float Ks[KV * KV];
    __shared__ float bs[KV];
    __shared__ Cls cl;
    for (int i = threadIdx.x; i < KV * KV; i += blockDim.x) Ks[i] = g_Kinv[c * KW * KW + i];
    if (threadIdx.x < KV) bs[threadIdx.x] = g_b[c * KW + threadIdx.x];
    if (threadIdx.x == 0) cl = g_cls[c];
    __syncthreads();
    if (q >= Qq) return;
    const float* Ur = g_U + (long long)q * NU + c * KW;
    float v[KV];
    float u33 = Ur[KW - 1];  // g . t_mu
#pragma unroll
    for (int i = 0; i < KV; i++) v[i] = Ur[i] - bs[i];  // u_a = t_a.(g - t_mu)
    float s = 0.f;
#pragma unroll 4
    for (int i = 0; i < KV; i++) {
        float acc = 0.f;
#pragma unroll
        for (int j = 0; j < KV; j++) acc += Ks[i * KV + j] * v[j];
        s += v[i] * acc;
    }
    float distA = g_Gn2[q] - 2.0f * u33 + cl.hh - s;
    float dist  = cl.invscale_half * distA
                + 0.5f * (g_qn2[q] - 2.0f * g_qm[q * Cc + c] + g_mun2[c]);
    out[(long long)q * Cc + c] = cl.bias - cl.coefD * log1pf(dist * cl.inv_common);
}

// ------------------------------ host launchers -------------------------------
static void sgemm_big_split(const float* A, long long sA, int lda,
                            const float* B, long long sB, int ldb,
                            float* part, float* out, long long sOut, int ldc,
                            int M, int N, int K, float alpha, bool transB, int pairs,
                            int nsplit, int kchunk, int kbmode, int kemode) {
    dim3 grid((N + 127) / 128, (M + 127) / 128, pairs * nsplit);
    if (transB)
        sgemm128_split_kernel<true><<<grid, 256>>>(A, sA, lda, B, sB, ldb, part,
                                                   M, N, K, nsplit, kchunk, kbmode, kemode);
    else
        sgemm128_split_kernel<false><<<grid, 256>>>(A, sA, lda, B, sB, ldb, part,
                                                    M, N, K, nsplit, kchunk, kbmode, kemode);
    long long total = (long long)pairs * M * N;
    reduce_kernel<<<(unsigned)((total + 255) / 256), 256>>>(part, out, nsplit, M, N, ldc,
                                                            sOut, alpha, pairs);
}

static void sgemm_big_direct(const float* A, long long sA, int lda,
                             const float* B, long long sB, int ldb,
                             float* Cmat, long long sC, int ldc,
                             int M, int N, int K, float alpha, bool transB, int pairs,
                             int kbmode, int kemode) {
    dim3 grid((N + 127) / 128, (M + 127) / 128, pairs);
    if (transB)
        sgemm128_direct_kernel<true><<<grid, 256>>>(A, sA, lda, B, sB, ldb, Cmat, sC, ldc,
                                                    M, N, K, alpha, kbmode, kemode);
    else
        sgemm128_direct_kernel<false><<<grid, 256>>>(A, sA, lda, B, sB, ldb, Cmat, sC, ldc,
                                                     M, N, K, alpha, kbmode, kemode);
}

extern "C" void kernel_launch(void* const* d_in, const int* in_sizes, int n_in,
                              void* d_out, int out_size) {
    const float* support = (const float*)d_in[0];
    const float* query   = (const float*)d_in[1];
    const int*   labels  = (const int*)d_in[2];
    const float* m       = (const float*)d_in[3];
    const float* kappa   = (const float*)d_in[4];
    const float* nu      = (const float*)d_in[5];
    const float* tdiag   = (const float*)d_in[6];
    const float* tlower  = (const float*)d_in[7];
    float* out = (float*)d_out;

    float *pL, *pLinv, *pTmp, *pW, *pTG, *pU, *pPart, *pTtT;
    cudaGetSymbolAddress((void**)&pL, g_L);
    cudaGetSymbolAddress((void**)&pLinv, g_Linv);
    cudaGetSymbolAddress((void**)&pTmp, g_Tmp);
    cudaGetSymbolAddress((void**)&pW, g_W);
    cudaGetSymbolAddress((void**)&pTG, g_TG);
    cudaGetSymbolAddress((void**)&pU, g_U);
    cudaGetSymbolAddress((void**)&pPart, g_Part);
    cudaGetSymbolAddress((void**)&pTtT, g_TtT);
    float* pT = pTG;                        // T: rows 0..NU-1
    float* pG = pTG + (long long)NU * Dd;   // G: rows NU..NU+Qq-1

    // 1) scalars, per-class params, parallel-rank sample gather, sum log|diag L|
    setup_kernel<<<1, NSUP>>>(labels, kappa, nu, tdiag);

    // 2) fused per-class xbar/mu + W = [X_c - xbar | sqrt(.)*(xbar-m) | mu_c]
    build_WM_kernel<<<(Cc * Dd + 255) / 256, 256>>>(support, m);

    // 3) L and L^{-1} (recursive-doubling blocked triangular inverse, 64-base)
    build_L_kernel<<<(Dd * Dd + 255) / 256, 256>>>(tdiag, tlower);
    inv_diag64_kernel<<<16, 64>>>();
    // s = 64 level (combine 64-blocks into 128-blocks): 8 pairs, direct
    {
        int s = 64, pairs = 8;
        long long stride = 2LL * s * (Dd + 1);
        sgemm_big_direct(pL + (long long)s * Dd, stride, Dd,
                         pLinv, stride, Dd,
                         pTmp, (long long)s * s, s,
                         s, s, s, 1.0f, false, pairs, 0, 0);
        sgemm_big_direct(pLinv + (long long)s * Dd + s, stride, Dd,
                         pTmp, (long long)s * s, s,
                         pLinv + (long long)s * Dd, stride, Dd,
                         s, s, s, -1.0f, false, pairs, 0, 0);
    }
    // s = 128 level: direct (4 pairs)
    {
        int s = 128, pairs = 4;
        long long stride = 2LL * s * (Dd + 1);
        sgemm_big_direct(pL + (long long)s * Dd, stride, Dd,
                         pLinv, stride, Dd,
                         pTmp, (long long)s * s, s,
                         s, s, s, 1.0f, false, pairs, 1, 0);
        sgemm_big_direct(pLinv + (long long)s * Dd + s, stride, Dd,
                         pTmp, (long long)s * s, s,
                         pLinv + (long long)s * Dd, stride, Dd,
                         s, s, s, -1.0f, false, pairs, 0, 1);
    }
    // s = 256, 512 levels: K-split fast core
    for (int lev = 4; lev <= 5; lev++) {
        int s = 32 << (lev - 1);
        int pairs = 32 >> lev;
        long long stride = 2LL * s * (Dd + 1);
        int nsplit = (s == 256) ? 4 : 8;
        int kchunk = s / nsplit;  // 64
        sgemm_big_split(pL + (long long)s * Dd, stride, Dd,
                        pLinv, stride, Dd,
                        pPart, pTmp, (long long)s * s, s,
                        s, s, s, 1.0f, false, pairs, nsplit, kchunk, 1, 0);
        sgemm_big_split(pLinv + (long long)s * Dd + s, stride, Dd,
                        pTmp, (long long)s * s, s,
                        pPart, pLinv + (long long)s * Dd, stride, Dd,
                        s, s, s, -1.0f, false, pairs, nsplit, kchunk, 0, 1);
    }

    // 4+5) fused K-split: [T; G] = [W; query] @ Linv^T  (stacked 2112 x 1024)
    {
        int nby1 = (NU + 127) / 128;       // 9
        int nby2 = (Qq + 127) / 128;       // 8
        dim3 grid(Dd / 128, nby1 + nby2, 2);  // (8, 17, 2)
        sgemm128_dual_split_kernel<<<grid, 256>>>(pW, nby1, query, pLinv, pPart, Dd / 2);
        long long total = (long long)NUQ * Dd;
        reduce_kernel<<<(unsigned)((total + 255) / 256), 256>>>(pPart, pTG, 2, NUQ, Dd, Dd,
                                                                0, 1.0f, 1);
    }

    // 6) all row norms in one launch: ||L^{-1}q||^2, ||q||^2, ||mu||^2
    rownorm_all_kernel<<<2 * Qq + Cc, 256>>>(pG, query);

    // 7) TtT per class via K-split Gram + reduce; then fp64 33x33 inverse
    gram_split_kernel<<<Cc * 4, 256>>>(pT, pPart, 4, Dd / 4);
    {
        long long total = (long long)Cc * KW * KW;
        reduce_kernel<<<(unsigned)((total + 255) / 256), 256>>>(pPart, pTtT, 4, KW, KW, KW,
                                                                (long long)KW * KW, 1.0f, Cc);
    }
    small_inv_kernel<<<Cc, 64>>>();

    // 8) U = G @ T^T  [1024 x 1088]  K-split x4
    sgemm_big_split(pG, 0, Dd, pT, 0, Dd,
                    pPart, pU, 0, NU,
                    Qq, NU, Dd, 1.0f, true, 1, 4, Dd / 4, 0, 0);

    // 9) qm = query @ mu^T  [Q x C]  skinny kernel
    qm_kernel<<<Qq / 8, 256>>>(query);

    // 10) fuse quadratic forms + bias + log1p
    finalize_kernel<<<dim3((Qq + 127) / 128, Cc), 128>>>(out);
}

// round 14
// speedup vs baseline: 1.9172x; 1.2526x over previous
#include <cuda_runtime.h>
#include <math.h>

// ---------------------------------------------------------------------------
// MetaQDA via conditioned Woodbury / matrix-determinant-lemma restructuring.
//   S_c = L L^T + V_c^T V_c,   V_c = [x_i - xbar (32 rows); sqrt(kappa*N/kN)(xbar - m)]
//   S^{-1} = L^{-T}(I - T^T M^{-1} T)L^{-1},  T = V L^{-T} (33 x D),  M = I + T T^T (SPD)
//   logdet S = 2 sum log|L_ii| + logdet M
// GEMM core: 128x128x8 double-buffered, packed fma.rn.f32x2, conflict-free.
// This round: no-pivot element-parallel fp64 GJ for M (SPD, lambda_min=1),
// triangle-aware uniform K=128 chunking for the dual GEMM (balanced waves),
// 4-way ILP in the 64x64 triangular diag inverse.
// ---------------------------------------------------------------------------

#define Dd   1024
#define Cc   32
#define SHOTSn 32
#define NSUP 1024
#define Qq   1024
#define KW   34     // rows of T-hat per class: 32 centered + scaled-diff + mu(aux)
#define KV   33     // rows entering the Woodbury capacitance M
#define NU   (Cc * KW)   // 1088
#define NUQ  (NU + Qq)   // 2112
#define DSPL 8           // dual K-split chunks (kchunk = 128)

// ------------------------- scratch (device globals) -------------------------
__device__ float g_L[Dd * Dd];
__device__ float g_Linv[Dd * Dd];
__device__ float g_Tmp[512 * 512];
__device__ float g_W[NU * Dd];
__device__ float g_TG[NUQ * Dd];        // T (first NU rows) then G (Qq rows)
__device__ float g_U[Qq * NU];          // [q][c*KW + k]
__device__ float g_Part[DSPL * NUQ * Dd];  // K-split partial buffer
__device__ float g_TtT[Cc * KW * KW];
__device__ float g_Kinv[Cc * KW * KW];  // packed KV x KV per class
__device__ float g_b[Cc * KW];
__device__ float g_mu[Cc * Dd];
__device__ float g_xbar[Cc * Dd];
__device__ float g_Gn2[Qq];
__device__ float g_qn2[Qq];
__device__ float g_mun2[Cc];
__device__ float g_qm[Qq * Cc];
__device__ int   g_sample_of[Cc * SHOTSn];

struct Cls {
    float Nj, kN, common_, scale;
    float bias, coefD, inv_common, invscale_half, hh;
};
__device__ Cls   g_cls[Cc];
__device__ float g_kappa_;
__device__ float g_sumlogL;

// ------------------------------ f32x2 helpers --------------------------------
__device__ __forceinline__ unsigned long long ffma2(unsigned long long a,
                                                    unsigned long long b,
                                                    unsigned long long c) {
    unsigned long long d;
    asm("fma.rn.f32x2 %0, %1, %2, %3;" : "=l"(d) : "l"(a), "l"(b), "l"(c));
    return d;
}
__device__ __forceinline__ unsigned long long pack2(float lo, float hi) {
    unsigned long long r;
    asm("mov.b64 %0, {%1, %2};" : "=l"(r) : "f"(lo), "f"(hi));
    return r;
}

// ------------------------------- setup --------------------------------------
__global__ void setup_kernel(const int* __restrict__ labels,
                             const float* __restrict__ kappa_p,
                             const float* __restrict__ nu_p,
                             const float* __restrict__ triu_diag) {
    __shared__ int   hist[32][33];   // [warp][class]
    __shared__ float red[32];
    int t = threadIdx.x;  // 1024 threads
    int w = t >> 5, lane = t & 31;
    hist[w][lane] = 0;
    g_sample_of[t] = 0;
    __syncthreads();

    int l = labels[t];
    unsigned mask = __match_any_sync(0xffffffffu, l);
    int intra = __popc(mask & ((1u << lane) - 1u));
    int leader = __ffs(mask) - 1;
    if (lane == leader && l >= 0 && l < Cc) hist[w][l] = __popc(mask);
    __syncthreads();
    if (l >= 0 && l < Cc) {
        int cnt = intra;
        for (int w2 = 0; w2 < w; w2++) cnt += hist[w2][l];
        if (cnt < SHOTSn) g_sample_of[l * SHOTSn + cnt] = t;
    }

    float v = logf(fabsf(triu_diag[t]));
    for (int o = 16; o > 0; o >>= 1) v += __shfl_down_sync(0xffffffffu, v, o);
    if (lane == 0) red[w] = v;
    __syncthreads();
    if (t < 32) {
        float s = red[t];
        for (int o = 16; o > 0; o >>= 1) s += __shfl_down_sync(0xffffffffu, s, o);
        if (t == 0) g_sumlogL = s;
    }

    if (t < Cc) {
        int nj = 0;
        for (int w2 = 0; w2 < 32; w2++) nj += hist[w2][t];
        float kappa_ = fabsf(*kappa_p) + 1e-6f;
        float nu_    = fmaxf(*nu_p, (float)(Dd - 1) + 1e-6f);
        float Njf = (float)nj;
        float kN = kappa_ + Njf;
        float common_ = nu_ + Njf + 1.0f - (float)Dd;
        float scale = (kN + 1.0f) / (common_ * kN);
        Cls c;
        c.Nj = Njf; c.kN = kN; c.common_ = common_; c.scale = scale;
        c.bias = 0.f;
        c.coefD = 0.5f * (common_ + (float)Dd);
        c.inv_common = 1.0f / common_;
        c.invscale_half = 0.5f / scale;
        c.hh = 0.f;
        g_cls[t] = c;
        if (t == 0) g_kappa_ = kappa_;
    }
}

// --------------------------- build L (and zero Linv) -------------------------
__global__ void build_L_kernel(const float* __restrict__ tdiag,
                               const float* __restrict__ tlower) {
    int idx = blockIdx.x * blockDim.x + threadIdx.x;
    if (idx >= Dd * Dd) return;
    int i = idx / Dd, j = idx % Dd;
    float v = (i == j) ? fabsf(tdiag[i]) : (i > j ? tlower[idx] : 0.0f);
    g_L[idx] = v;
    g_Linv[idx] = 0.0f;
}

// --------- invert 64x64 lower-triangular diagonal blocks (registers) ---------
// 4 independent accumulators break the serial FMA chain (throughput-bound).
__global__ void inv_diag64_kernel() {
    __shared__ float Ls[64][65];
    __shared__ float rd[64];
    int b = blockIdx.x, t = threadIdx.x;  // 64 threads
    int off = b * 64;
    for (int i = 0; i < 64; i++) Ls[i][t] = g_L[(long long)(off + i) * Dd + off + t];
    __syncthreads();
    rd[t] = 1.0f / Ls[t][t];
    __syncthreads();
    float x[64];
#pragma unroll
    for (int i = 0; i < 64; i++) {
        float s0 = (t == i) ? 1.0f : 0.0f, s1 = 0.f, s2 = 0.f, s3 = 0.f;
        int k = 0;
#pragma unroll 4
        for (; k + 3 < i; k += 4) {
            s0 -= Ls[i][k + 0] * x[k + 0];
            s1 -= Ls[i][k + 1] * x[k + 1];
            s2 -= Ls[i][k + 2] * x[k + 2];
            s3 -= Ls[i][k + 3] * x[k + 3];
        }
        for (; k < i; k++) s0 -= Ls[i][k] * x[k];
        x[i] = ((s0 + s1) + (s2 + s3)) * rd[i];
    }
#pragma unroll
    for (int i = 0; i < 64; i++)
        g_Linv[(long long)(off + i) * Dd + off + t] = x[i];
}

// -------- fast SGEMM core (128x128x8, 8x8 via f32x2, dbuf, conflict-free) ----
template <bool TRANSB>
__device__ __forceinline__ void sgemm128_core(
    const float* __restrict__ A, int lda,
    const float* __restrict__ B, int ldb,
    float* __restrict__ Cp, int ldc,
    int M, int N, float alpha, int m0, int n0, int kbeg, int kend) {
    __shared__ __align__(16) float Asd[2][8][264];  // [k][2*m] duplicated
    __shared__ __align__(16) float Bs[2][8][132];   // [k][n]
    const int tid = threadIdx.x;              // 256
    const int tx = tid & 15, ty = tid >> 4;
    const int arow = tid >> 1, ak4 = (tid & 1) * 4;   // A (and B if TRANSB) loads
    const int bk = tid >> 5, bn4 = (tid & 31) * 4;    // B loads if !TRANSB

    unsigned long long acc2[8][4] = {};  // 8 m-rows x 4 packed n-pairs

    if (kend > kbeg) {
        const int t0 = kbeg >> 3, t1 = kend >> 3;
        float4 ar, br;
        const float4 fz = make_float4(0.f, 0.f, 0.f, 0.f);

        ar = (m0 + arow < M) ? *(const float4*)(A + (long long)(m0 + arow) * lda + kbeg + ak4) : fz;
        if (TRANSB) {
            br = (n0 + arow < N) ? *(const float4*)(B + (long long)(n0 + arow) * ldb + kbeg + ak4) : fz;
        } else {
            if (n0 + bn4 + 3 < N) {
                br = *(const float4*)(B + (long long)(kbeg + bk) * ldb + n0 + bn4);
            } else {
                const float* Bp = B + (long long)(kbeg + bk) * ldb;
                br.x = (n0 + bn4 + 0 < N) ? Bp[n0 + bn4 + 0] : 0.f;
                br.y = (n0 + bn4 + 1 < N) ? Bp[n0 + bn4 + 1] : 0.f;
                br.z = (n0 + bn4 + 2 < N) ? Bp[n0 + bn4 + 2] : 0.f;
                br.w = (n0 + bn4 + 3 < N) ? Bp[n0 + bn4 + 3] : 0.f;
            }
        }
        *(float2*)&Asd[0][ak4 + 0][2 * arow] = make_float2(ar.x, ar.x);
        *(float2*)&Asd[0][ak4 + 1][2 * arow] = make_float2(ar.y, ar.y);
        *(float2*)&Asd[0][ak4 + 2][2 * arow] = make_float2(ar.z, ar.z);
        *(float2*)&Asd[0][ak4 + 3][2 * arow] = make_float2(ar.w, ar.w);
        if (TRANSB) {
            Bs[0][ak4 + 0][arow] = br.x; Bs[0][ak4 + 1][arow] = br.y;
            Bs[0][ak4 + 2][arow] = br.z; Bs[0][ak4 + 3][arow] = br.w;
        } else {
            *(float4*)&Bs[0][bk][bn4] = br;
        }
        __syncthreads();

        for (int t = t0; t < t1; t++) {
            const int buf = (t - t0) & 1;
            const int kn = (t + 1) << 3;
            if (t + 1 < t1) {
                ar = (m0 + arow < M) ? *(const float4*)(A + (long long)(m0 + arow) * lda + kn + ak4) : fz;
                if (TRANSB) {
                    br = (n0 + arow < N) ? *(const float4*)(B + (long long)(n0 + arow) * ldb + kn + ak4) : fz;
                } else {
                    if (n0 + bn4 + 3 < N) {
                        br = *(const float4*)(B + (long long)(kn + bk) * ldb + n0 + bn4);
                    } else {
                        const float* Bp = B + (long long)(kn + bk) * ldb;
                        br.x = (n0 + bn4 + 0 < N) ? Bp[n0 + bn4 + 0] : 0.f;
                        br.y = (n0 + bn4 + 1 < N) ? Bp[n0 + bn4 + 1] : 0.f;
                        br.z = (n0 + bn4 + 2 < N) ? Bp[n0 + bn4 + 2] : 0.f;
                        br.w = (n0 + bn4 + 3 < N) ? Bp[n0 + bn4 + 3] : 0.f;
                    }
                }
            }
#pragma unroll
            for (int k = 0; k < 8; k++) {
                unsigned long long a2[8], b2[4];
#pragma unroll
                for (int i = 0; i < 8; i++)
                    a2[i] = *(const unsigned long long*)&Asd[buf][k][(ty * 8 + i) * 2];
                float4 bf0 = *(const float4*)&Bs[buf][k][tx * 8];
                float4 bf1 = *(const float4*)&Bs[buf][k][tx * 8 + 4];
                b2[0] = pack2(bf0.x, bf0.y);
                b2[1] = pack2(bf0.z, bf0.w);
                b2[2] = pack2(bf1.x, bf1.y);
                b2[3] = pack2(bf1.z, bf1.w);
#pragma unroll
                for (int i = 0; i < 8; i++)
#pragma unroll
                    for (int j = 0; j < 4; j++) acc2[i][j] = ffma2(a2[i], b2[j], acc2[i][j]);
            }
            if (t + 1 < t1) {
                const int b2i = (t + 1 - t0) & 1;
                *(float2*)&Asd[b2i][ak4 + 0][2 * arow] = make_float2(ar.x, ar.x);
                *(float2*)&Asd[b2i][ak4 + 1][2 * arow] = make_float2(ar.y, ar.y);
                *(float2*)&Asd[b2i][ak4 + 2][2 * arow] = make_float2(ar.z, ar.z);
                *(float2*)&Asd[b2i][ak4 + 3][2 * arow] = make_float2(ar.w, ar.w);
                if (TRANSB) {
                    Bs[b2i][ak4 + 0][arow] = br.x; Bs[b2i][ak4 + 1][arow] = br.y;
                    Bs[b2i][ak4 + 2][arow] = br.z; Bs[b2i][ak4 + 3][arow] = br.w;
                } else {
                    *(float4*)&Bs[b2i][bk][bn4] = br;
                }
            }
            __syncthreads();
        }
    }

#pragma unroll
    for (int i = 0; i < 8; i++) {
        int m = m0 + ty * 8 + i;
        if (m >= M) continue;
        float* Cr = Cp + (long long)m * ldc;
#pragma unroll
        for (int j = 0; j < 4; j++) {
            int n = n0 + tx * 8 + 2 * j;
            float lo = __uint_as_float((unsigned int)acc2[i][j]);
            float hi = __uint_as_float((unsigned int)(acc2[i][j] >> 32));
            if (n < N)     Cr[n]     = alpha * lo;
            if (n + 1 < N) Cr[n + 1] = alpha * hi;
        }
    }
}

// -------------------- K-split wrapper: writes partial chunks -----------------
template <bool TRANSB>
__global__ __launch_bounds__(256)
void sgemm128_split_kernel(const float* __restrict__ A, long long sA, int lda,
                           const float* __restrict__ B, long long sB, int ldb,
                           float* __restrict__ part,
                           int M, int N, int K, int nsplit, int kchunk,
                           int kbmode, int kemode) {
    int pair = blockIdx.z / nsplit;
    int chunk = blockIdx.z % nsplit;
    int m0 = blockIdx.y * 128, n0 = blockIdx.x * 128;
    int kb = chunk * kchunk;
    int ke = min(kb + kchunk, K);
    if (kbmode == 1) kb = max(kb, n0);
    if (kemode == 1) ke = min(ke, m0 + 128);
    float* Cp = part + (long long)blockIdx.z * M * N;
    sgemm128_core<TRANSB>(A + pair * sA, lda, B + pair * sB, ldb,
                          Cp, N, M, N, 1.0f, m0, n0, kb, ke);
}

// -------------------- direct (no-split) wrapper ------------------------------
template <bool TRANSB>
__global__ __launch_bounds__(256)
void sgemm128_direct_kernel(const float* __restrict__ A, long long sA, int lda,
                            const float* __restrict__ B, long long sB, int ldb,
                            float* __restrict__ Cp, long long sC, int ldc,
                            int M, int N, int K, float alpha, int kbmode, int kemode) {
    int m0 = blockIdx.y * 128, n0 = blockIdx.x * 128;
    int kb = (kbmode == 1) ? n0 : 0;
    int ke = (kemode == 1) ? min(K, m0 + 128) : K;
    sgemm128_core<TRANSB>(A + blockIdx.z * sA, lda, B + blockIdx.z * sB, ldb,
                          Cp + blockIdx.z * sC, ldc, M, N, alpha, m0, n0, kb, ke);
}

// Fused T|G (stacked) = [W; query] @ Linv^T, uniform K=128 chunks with
// triangle-aware validity: chunk p covers k in [128p, 128p+128), valid iff
// p <= column block j (Linv lower-tri). Invalid blocks retire immediately.
__global__ __launch_bounds__(256)
void sgemm128_dual_split_kernel(const float* __restrict__ A1, int nby1,
                                const float* __restrict__ A2,
                                const float* __restrict__ B,
                                float* __restrict__ part) {
    int chunk = blockIdx.z;
    int n0 = blockIdx.x * 128;
    int kb = chunk * 128;
    if (kb > n0) return;                 // chunk past the triangle: no work
    int ke = kb + 128;
    const float* A;
    int M, m0, rowoff;
    if ((int)blockIdx.y < nby1) {
        A = A1; M = NU; m0 = blockIdx.y * 128; rowoff = 0;
    } else {
        A = A2; M = Qq; m0 = (blockIdx.y - nby1) * 128; rowoff = NU;
    }
    float* Cp = part + (long long)chunk * NUQ * Dd + (long long)rowoff * Dd;
    sgemm128_core<true>(A, Dd, B, Dd, Cp, Dd, M, Dd, 1.0f, m0, n0, kb, ke);
}

// ---- triangle-aware reduce for dual: column j sums chunks 0..j only --------
__global__ void reduce_tri_kernel(const float* __restrict__ part, float* __restrict__ out) {
    long long idx = (long long)blockIdx.x * blockDim.x + threadIdx.x;
    long long total = (long long)NUQ * Dd;
    if (idx >= total) return;
    int nn = (int)(idx % Dd);
    int cnt = (nn >> 7) + 1;            // column block j = nn/128 -> j+1 chunks
    const float* p = part + idx;
    float s = 0.f;
    for (int c = 0; c < cnt; c++) s += p[(long long)c * NUQ * Dd];
    out[idx] = s;
}

// -------------------- reduce partial chunks into output ----------------------
__global__ void reduce_kernel(const float* __restrict__ part, float* __restrict__ out,
                              int nsplit, int M, int N, int ldc, long long sOut,
                              float alpha, int pairs) {
    long long idx = (long long)blockIdx.x * blockDim.x + threadIdx.x;
    long long total = (long long)pairs * M * N;
    if (idx >= total) return;
    int pair = (int)(idx / ((long long)M * N));
    long long rem = idx - (long long)pair * M * N;
    int mm = (int)(rem / N);
    int nn = (int)(rem - (long long)mm * N);
    const float* p = part + (long long)pair * nsplit * M * N + rem;
    float s = 0.f;
    for (int c = 0; c < nsplit; c++) s += p[(long long)c * M * N];
    out[pair * sOut + (long long)mm * ldc + nn] = alpha * s;
}

// ----------------- fused per-class means + W build ---------------------------
__global__ void build_WM_kernel(const float* __restrict__ support,
                                const float* __restrict__ m) {
    int idx = blockIdx.x * blockDim.x + threadIdx.x;  // over C * D
    if (idx >= Cc * Dd) return;
    int c = idx / Dd, d = idx % Dd;
    const int* so = g_sample_of + c * SHOTSn;
    float mv = m[d];
    float s = 0.f;
#pragma unroll 4
    for (int j = 0; j < SHOTSn; j++)
        s += support[(long long)so[j] * Dd + d];
    Cls cl = g_cls[c];
    float xbar = s / cl.Nj;
    float mu = (g_kappa_ * mv + s) / cl.kN;
    g_xbar[idx] = xbar;
    g_mu[idx] = mu;
    float* Wc = g_W + (long long)(c * KW) * Dd + d;
#pragma unroll 4
    for (int k = 0; k < SHOTSn; k++)
        Wc[(long long)k * Dd] = support[(long long)so[k] * Dd + d] - xbar;
    float c2 = sqrtf(g_kappa_ * cl.Nj / cl.kN);
    Wc[(long long)SHOTSn * Dd] = c2 * (xbar - mv);
    Wc[(long long)(SHOTSn + 1) * Dd] = mu;
}

// ---------------- all row norms in one launch (G, query, mu) -----------------
__global__ void rownorm_all_kernel(const float* __restrict__ G,
                                   const float* __restrict__ query) {
    int r = blockIdx.x, t = threadIdx.x;  // 256 threads
    const float* row;
    float* dst;
    if (r < Qq)            { row = G + (long long)r * Dd;            dst = g_Gn2 + r; }
    else if (r < 2 * Qq)   { row = query + (long long)(r - Qq) * Dd; dst = g_qn2 + (r - Qq); }
    else                   { row = g_mu + (long long)(r - 2 * Qq) * Dd; dst = g_mun2 + (r - 2 * Qq); }
    float s = 0.f;
    for (int j = t; j < Dd; j += blockDim.x) { float v = row[j]; s += v * v; }
    __shared__ float red[8];
    for (int o = 16; o > 0; o >>= 1) s += __shfl_down_sync(0xffffffffu, s, o);
    if ((t & 31) == 0) red[t >> 5] = s;
    __syncthreads();
    if (t < 32) {
        float v = (t < 8) ? red[t] : 0.f;
        for (int o = 4; o > 0; o >>= 1) v += __shfl_down_sync(0xffffffffu, v, o);
        if (t == 0) *dst = v;
    }
}

// ---------------- K-split Gram: TtT partials per (class, chunk) --------------
__global__ void gram_split_kernel(const float* __restrict__ T,
                                  float* __restrict__ part,
                                  int nsplit, int kchunk) {
    __shared__ __align__(16) float Ts[KW][256 + 4];
    int c = blockIdx.x / nsplit;
    int chunk = blockIdx.x % nsplit;
    int tid = threadIdx.x;  // 256
    const float* Tc = T + (long long)(c * KW) * Dd + chunk * kchunk;
    for (int i = tid; i < KW * (kchunk / 4); i += blockDim.x) {
        int row = i / (kchunk / 4), k4 = (i % (kchunk / 4)) * 4;
        *(float4*)&Ts[row][k4] = *(const float4*)(Tc + (long long)row * Dd + k4);
    }
    __syncthreads();
    float* outp = part + (long long)blockIdx.x * KW * KW;
    for (int e = tid; e < KW * KW; e += blockDim.x) {
        int i = e / KW, j = e % KW;
        float s = 0.f;
        for (int k = 0; k < kchunk; k += 4) {
            float4 a = *(const float4*)&Ts[i][k];
            float4 b = *(const float4*)&Ts[j][k];
            s += a.x * b.x + a.y * b.y + a.z * b.z + a.w * b.w;
        }
        outp[e] = s;
    }
}

// ------------------------- skinny qm = query @ mu^T --------------------------
__global__ void qm_kernel(const float* __restrict__ query) {
    __shared__ __align__(16) float mus[32][68];
    int tid = threadIdx.x;  // 256
    int c = tid & 31, qi = tid >> 5;  // 8 q per block
    int q = blockIdx.x * 8 + qi;
    float acc = 0.f;
    for (int k0 = 0; k0 < Dd; k0 += 64) {
        for (int i = tid; i < 32 * 16; i += 256) {
            int row = i / 16, k4 = (i % 16) * 4;
            *(float4*)&mus[row][k4] = *(const float4*)(g_mu + (long long)row * Dd + k0 + k4);
        }
        __syncthreads();
        const float* qr = query + (long long)q * Dd + k0;
#pragma unroll
        for (int k = 0; k < 64; k += 4) {
            float4 qv = *(const float4*)(qr + k);     // broadcast across warp
            float4 mv = *(const float4*)&mus[c][k];
            acc += qv.x * mv.x + qv.y * mv.y + qv.z * mv.z + qv.w * mv.w;
        }
        __syncthreads();
    }
    g_qm[(long long)q * Cc + c] = acc;
}

// ---- per-class SPD 33x33 inverse: no-pivot element-parallel fp64 GJ ---------
// M = I + T T^T is SPD with lambda_min = 1: pivoting unnecessary, all pivots
// positive. 256 threads; save-column-k trick; 3 syncs/iteration.
__global__ void small_inv_kernel() {
    int c = blockIdx.x, t = threadIdx.x;  // 256 threads
    __shared__ double Ms[KV][KV + 1];
    __shared__ double Iv[KV][KV + 1];
    __shared__ double colk[KV];
    __shared__ double s_logdet;
    const float* TtT = g_TtT + c * KW * KW;
    for (int i = t; i < KV * KV; i += blockDim.x) {
        int r = i / KV, cc = i % KV;
        Ms[r][cc] = (double)TtT[r * KW + cc] + (r == cc ? 1.0 : 0.0);  // M = I + T T^T
        Iv[r][cc] = (r == cc) ? 1.0 : 0.0;
    }
    if (t < KV) g_b[c * KW + t] = TtT[t * KW + (KW - 1)];  // t_a . t_mu
    if (t == 0) s_logdet = 0.0;
    __syncthreads();
    for (int k = 0; k < KV; k++) {
        if (t < KV) colk[t] = Ms[t][k];
        if (t == 0) s_logdet += log(Ms[k][k]);
        __syncthreads();
        double pivinv = 1.0 / colk[k];
        if (t < KV) { Ms[k][t] *= pivinv; Iv[k][t] *= pivinv; }
        __syncthreads();
        for (int e = t; e < KV * KV; e += blockDim.x) {
            int r = e / KV, j = e % KV;
            if (r != k) {
                double f = colk[r];
                Ms[r][j] -= f * Ms[k][j];
                Iv[r][j] -= f * Iv[k][j];
            }
        }
        __syncthreads();
    }
    for (int i = t; i < KV * KV; i += blockDim.x)
        g_Kinv[c * KW * KW + i] = (float)Iv[i / KV][i % KV];
    if (t == 0) {
        Cls cl = g_cls[c];
        double logdetS = 2.0 * (double)g_sumlogL + s_logdet;
        double logdet_sigma = (double)Dd * log((double)cl.scale) + logdetS;
        double common_ = (double)cl.common_;
        double bias = lgamma(0.5 * (common_ + (double)Dd)) - lgamma(0.5 * common_)
                    - 0.5 * (double)Dd * log(common_) - 0.5 * logdet_sigma;
        g_cls[c].bias = (float)bias;
        g_cls[c].hh = TtT[(KW - 1) * KW + (KW - 1)];  // ||t_mu||^2
    }
}

// --------------------------------- finalize ----------------------------------
__global__ void finalize_kernel(float* __restrict__ out) {
    int c = blockIdx.y;
    int q = blockIdx.x * blockDim.x + threadIdx.x;
    __shared__ float Ks[KV * KV];
    __shared__ float bs[KV];
    __shared__ Cls cl;
    for (int i = threadIdx.x; i < KV * KV; i += blockDim.x) Ks[i] = g_Kinv[c * KW * KW + i];
    if (threadIdx.x < KV) bs[threadIdx.x] = g_b[c * KW + threadIdx.x];
    if (threadIdx.x == 0) cl = g_cls[c];
    __syncthreads();
    if (q >= Qq) return;
    const float* Ur = g_U + (long long)q * NU + c * KW;
    float v[KV];
    float u33 = Ur[KW - 1];  // g . t_mu
#pragma unroll
    for (int i = 0; i < KV; i++) v[i] = Ur[i] - bs[i];  // u_a = t_a.(g - t_mu)
    float s = 0.f;
#pragma unroll 4
    for (int i = 0; i < KV; i++) {
        float acc = 0.f;
#pragma unroll
        for (int j = 0; j < KV; j++) acc += Ks[i * KV + j] * v[j];
        s += v[i] * acc;
    }
    float distA = g_Gn2[q] - 2.0f * u33 + cl.hh - s;
    float dist  = cl.invscale_half * distA
                + 0.5f * (g_qn2[q] - 2.0f * g_qm[q * Cc + c] + g_mun2[c]);
    out[(long long)q * Cc + c] = cl.bias - cl.coefD * log1pf(dist * cl.inv_common);
}

// ------------------------------ host launchers -------------------------------
static void sgemm_big_split(const float* A, long long sA, int lda,
                            const float* B, long long sB, int ldb,
                            float* part, float* out, long long sOut, int ldc,
                            int M, int N, int K, float alpha, bool transB, int pairs,
                            int nsplit, int kchunk, int kbmode, int kemode) {
    dim3 grid((N + 127) / 128, (M + 127) / 128, pairs * nsplit);
    if (transB)
        sgemm128_split_kernel<true><<<grid, 256>>>(A, sA, lda, B, sB, ldb, part,
                                                   M, N, K, nsplit, kchunk, kbmode, kemode);
    else
        sgemm128_split_kernel<false><<<grid, 256>>>(A, sA, lda, B, sB, ldb, part,
                                                    M, N, K, nsplit, kchunk, kbmode, kemode);
    long long total = (long long)pairs * M * N;
    reduce_kernel<<<(unsigned)((total + 255) / 256), 256>>>(part, out, nsplit, M, N, ldc,
                                                            sOut, alpha, pairs);
}

static void sgemm_big_direct(const float* A, long long sA, int lda,
                             const float* B, long long sB, int ldb,
                             float* Cmat, long long sC, int ldc,
                             int M, int N, int K, float alpha, bool transB, int pairs,
                             int kbmode, int kemode) {
    dim3 grid((N + 127) / 128, (M + 127) / 128, pairs);
    if (transB)
        sgemm128_direct_kernel<true><<<grid, 256>>>(A, sA, lda, B, sB, ldb, Cmat, sC, ldc,
                                                    M, N, K, alpha, kbmode, kemode);
    else
        sgemm128_direct_kernel<false><<<grid, 256>>>(A, sA, lda, B, sB, ldb, Cmat, sC, ldc,
                                                     M, N, K, alpha, kbmode, kemode);
}

extern "C" void kernel_launch(void* const* d_in, const int* in_sizes, int n_in,
                              void* d_out, int out_size) {
    const float* support = (const float*)d_in[0];
    const float* query   = (const float*)d_in[1];
    const int*   labels  = (const int*)d_in[2];
    const float* m       = (const float*)d_in[3];
    const float* kappa   = (const float*)d_in[4];
    const float* nu      = (const float*)d_in[5];
    const float* tdiag   = (const float*)d_in[6];
    const float* tlower  = (const float*)d_in[7];
    float* out = (float*)d_out;

    float *pL, *pLinv, *pTmp, *pW, *pTG, *pU, *pPart, *pTtT;
    cudaGetSymbolAddress((void**)&pL, g_L);
    cudaGetSymbolAddress((void**)&pLinv, g_Linv);
    cudaGetSymbolAddress((void**)&pTmp, g_Tmp);
    cudaGetSymbolAddress((void**)&pW, g_W);
    cudaGetSymbolAddress((void**)&pTG, g_TG);
    cudaGetSymbolAddress((void**)&pU, g_U);
    cudaGetSymbolAddress((void**)&pPart, g_Part);
    cudaGetSymbolAddress((void**)&pTtT, g_TtT);
    float* pT = pTG;                        // T: rows 0..NU-1
    float* pG = pTG + (long long)NU * Dd;   // G: rows NU..NU+Qq-1

    // 1) scalars, per-class params, parallel-rank sample gather, sum log|diag L|
    setup_kernel<<<1, NSUP>>>(labels, kappa, nu, tdiag);

    // 2) fused per-class xbar/mu + W = [X_c - xbar | sqrt(.)*(xbar-m) | mu_c]
    build_WM_kernel<<<(Cc * Dd + 255) / 256, 256>>>(support, m);

    // 3) L and L^{-1} (recursive-doubling blocked triangular inverse, 64-base)
    build_L_kernel<<<(Dd * Dd + 255) / 256, 256>>>(tdiag, tlower);
    inv_diag64_kernel<<<16, 64>>>();
    // s = 64 level (combine 64-blocks into 128-blocks): 8 pairs, direct
    {
        int s = 64, pairs = 8;
        long long stride = 2LL * s * (Dd + 1);
        sgemm_big_direct(pL + (long long)s * Dd, stride, Dd,
                         pLinv, stride, Dd,
                         pTmp, (long long)s * s, s,
                         s, s, s, 1.0f, false, pairs, 0, 0);
        sgemm_big_direct(pLinv + (long long)s * Dd + s, stride, Dd,
                         pTmp, (long long)s * s, s,
                         pLinv + (long long)s * Dd, stride, Dd,
                         s, s, s, -1.0f, false, pairs, 0, 0);
    }
    // s = 128 level: direct (4 pairs)
    {
        int s = 128, pairs = 4;
        long long stride = 2LL * s * (Dd + 1);
        sgemm_big_direct(pL + (long long)s * Dd, stride, Dd,
                         pLinv, stride, Dd,
                         pTmp, (long long)s * s, s,
                         s, s, s, 1.0f, false, pairs, 1, 0);
        sgemm_big_direct(pLinv + (long long)s * Dd + s, stride, Dd,
                         pTmp, (long long)s * s, s,
                         pLinv + (long long)s * Dd, stride, Dd,
                         s, s, s, -1.0f, false, pairs, 0, 1);
    }
    // s = 256, 512 levels: K-split fast core
    for (int lev = 4; lev <= 5; lev++) {
        int s = 32 << (lev - 1);
        int pairs = 32 >> lev;
        long long stride = 2LL * s * (Dd + 1);
        int nsplit = (s == 256) ? 4 : 8;
        int kchunk = s / nsplit;  // 64
        sgemm_big_split(pL + (long long)s * Dd, stride, Dd,
                        pLinv, stride, Dd,
                        pPart, pTmp, (long long)s * s, s,
                        s, s, s, 1.0f, false, pairs, nsplit, kchunk, 1, 0);
        sgemm_big_split(pLinv + (long long)s * Dd + s, stride, Dd,
                        pTmp, (long long)s * s, s,
                        pPart, pLinv + (long long)s * Dd, stride, Dd,
                        s, s, s, -1.0f, false, pairs, nsplit, kchunk, 0, 1);
    }

    // 4+5) fused: [T; G] = [W; query] @ Linv^T, uniform K=128 chunks,
    // triangle-aware validity + reduce (balanced waves)
    {
        int nby1 = (NU + 127) / 128;       // 9
        int nby2 = (Qq + 127) / 128;       // 8
        dim3 grid(Dd / 128, nby1 + nby2, DSPL);  // (8, 17, 8)
        sgemm128_dual_split_kernel<<<grid, 256>>>(pW, nby1, query, pLinv, pPart);
        long long total = (long long)NUQ * Dd;
        reduce_tri_kernel<<<(unsigned)((total + 255) / 256), 256>>>(pPart, pTG);
    }

    // 6) all row norms in one launch: ||L^{-1}q||^2, ||q||^2, ||mu||^2
    rownorm_all_kernel<<<2 * Qq + Cc, 256>>>(pG, query);

    // 7) TtT per class via K-split Gram + reduce; then no-pivot fp64 33x33 GJ
    gram_split_kernel<<<Cc * 4, 256>>>(pT, pPart, 4, Dd / 4);
    {
        long long total = (long long)Cc * KW * KW;
        reduce_kernel<<<(unsigned)((total + 255) / 256), 256>>>(pPart, pTtT, 4, KW, KW, KW,
                                                                (long long)KW * KW, 1.0f, Cc);
    }
    small_inv_kernel<<<Cc, 256>>>();

    // 8) U = G @ T^T  [1024 x 1088]  K-split x4
    sgemm_big_split(pG, 0, Dd, pT, 0, Dd,
                    pPart, pU, 0, NU,
                    Qq, NU, Dd, 1.0f, true, 1, 4, Dd / 4, 0, 0);

    // 9) qm = query @ mu^T  [Q x C]  skinny kernel
    qm_kernel<<<Qq / 8, 256>>>(query);

    // 10) fuse quadratic forms + bias + log1p
    finalize_kernel<<<dim3((Qq + 127) / 128, Cc), 128>>>(out);
}